// round 9
// baseline (speedup 1.0000x reference)
#include <cuda_runtime.h>
#include <math.h>

#define Bn 8
#define Cc 96
#define C2 192
#define Npix 3136
#define KK 9
#define BNtot 25088       // Bn*Npix
#define NB_N 25           // ceil(3136/128) n-blocks in sgemm
#define PS_STRIDE (Bn*NB_N)  // 200 partials per channel

// ---------------- scratch ----------------
__device__ float g_h  [Bn*Cc*Npix];
__device__ float g_ht [Bn*Npix*Cc];
__device__ float g_xnt[Bn*Npix*Cc];     // L2-normalized features, (B,N,C)
__device__ float g_sq [Bn*Npix];
__device__ int   g_idx[Bn*Npix*KK];
__device__ float g_val2[Bn*2*Npix*KK];  // per-split top-9 values
__device__ int   g_idx2[Bn*2*Npix*KK];  // per-split top-9 indices
__device__ float g_y  [Bn*C2*Npix];
__device__ float g_t1 [Bn*C2*Npix];
__device__ float g_ps [C2*PS_STRIDE];
__device__ float g_pss[C2*PS_STRIDE];
__device__ float g_scale[C2];
__device__ float g_shift[C2];

// ---------------- SGEMM + fused BN partial stats (no bias: BN cancels it) ----------------
#define GM_BM 96
#define GM_BN 128
#define GM_BK 16

__global__ __launch_bounds__(256) void sgemm_bn_kernel(
    const float* __restrict__ W, const float* __restrict__ Act,
    float* __restrict__ Out, float* __restrict__ ps, float* __restrict__ pss,
    int M, int Kd)
{
    int b  = blockIdx.z;
    int m0 = blockIdx.y * GM_BM;
    int n0 = blockIdx.x * GM_BN;
    const float* Bm = Act + (size_t)b * Kd * Npix;
    float* C = Out + (size_t)b * M * Npix;

    __shared__ float As[GM_BK][GM_BM + 4];
    __shared__ float Bs[GM_BK][GM_BN];

    int tid = threadIdx.x;
    int tx = tid & 15, ty = tid >> 4;
    float acc[6][8];
    #pragma unroll
    for (int i = 0; i < 6; i++)
        #pragma unroll
        for (int j = 0; j < 8; j++) acc[i][j] = 0.f;

    for (int k0 = 0; k0 < Kd; k0 += GM_BK) {
        for (int e = tid; e < GM_BM * GM_BK; e += 256) {
            int m = e >> 4, k = e & 15;
            As[k][m] = W[(size_t)(m0 + m) * Kd + k0 + k];
        }
        for (int e = tid; e < GM_BK * GM_BN; e += 256) {
            int k = e >> 7, n = e & 127;
            int gn = n0 + n;
            Bs[k][n] = (gn < Npix) ? Bm[(size_t)(k0 + k) * Npix + gn] : 0.f;
        }
        __syncthreads();
        #pragma unroll
        for (int k = 0; k < GM_BK; k++) {
            float av[6];
            #pragma unroll
            for (int i = 0; i < 6; i++) av[i] = As[k][ty * 6 + i];
            float4 b0 = *(const float4*)&Bs[k][tx * 8];
            float4 b1 = *(const float4*)&Bs[k][tx * 8 + 4];
            float bv[8] = {b0.x, b0.y, b0.z, b0.w, b1.x, b1.y, b1.z, b1.w};
            #pragma unroll
            for (int i = 0; i < 6; i++)
                #pragma unroll
                for (int j = 0; j < 8; j++) acc[i][j] += av[i] * bv[j];
        }
        __syncthreads();
    }

    int nbase = n0 + tx * 8;
    #pragma unroll
    for (int i = 0; i < 6; i++) {
        int gm = m0 + ty * 6 + i;
        float s = 0.f, ss = 0.f;
        #pragma unroll
        for (int j = 0; j < 8; j++) {
            if (nbase + j < Npix) {
                float v = acc[i][j];
                s += v; ss += v * v;
            }
        }
        if (nbase + 3 < Npix) {
            float4 o = {acc[i][0], acc[i][1], acc[i][2], acc[i][3]};
            *(float4*)&C[(size_t)gm * Npix + nbase] = o;
        }
        if (nbase + 7 < Npix) {
            float4 o = {acc[i][4], acc[i][5], acc[i][6], acc[i][7]};
            *(float4*)&C[(size_t)gm * Npix + nbase + 4] = o;
        }
        #pragma unroll
        for (int off = 8; off > 0; off >>= 1) {
            s  += __shfl_down_sync(0xffffffffu, s,  off, 16);
            ss += __shfl_down_sync(0xffffffffu, ss, off, 16);
        }
        if (tx == 0) {
            size_t slot = (size_t)gm * PS_STRIDE + b * NB_N + blockIdx.x;
            ps[slot]  = s;
            pss[slot] = ss;
        }
    }
}

// ---------------- BN finalize ----------------
__global__ void bn_finalize_kernel(
    const float* __restrict__ ps, const float* __restrict__ pss,
    const float* __restrict__ g, const float* __restrict__ be,
    float* __restrict__ scale, float* __restrict__ shift, int C)
{
    int c = blockIdx.x * blockDim.x + threadIdx.x;
    if (c >= C) return;
    float s = 0.f, ss = 0.f;
    for (int i = 0; i < PS_STRIDE; i++) { s += ps[(size_t)c * PS_STRIDE + i]; ss += pss[(size_t)c * PS_STRIDE + i]; }
    float mean = s * (1.0f / (float)BNtot);
    float var  = ss * (1.0f / (float)BNtot) - mean * mean;
    float inv  = rsqrtf(var + 1e-5f);
    float sc = g[c] * inv;
    scale[c] = sc;
    shift[c] = be[c] - mean * sc;
}

// ---------------- BN apply + transpose + L2 normalize ----------------
#define BS_STRIDE 67
__global__ __launch_bounds__(256) void bn_norm_kernel(
    const float* __restrict__ Hraw, const float* __restrict__ scale, const float* __restrict__ shift,
    float* __restrict__ Ht, float* __restrict__ Xnt, float* __restrict__ Sq)
{
    __shared__ float S[Cc * BS_STRIDE];
    __shared__ float R[256];
    __shared__ float RN[64];
    int tid = threadIdx.x;
    int b = blockIdx.y;
    int n0 = blockIdx.x * 64;

    for (int e = tid; e < Cc * 64; e += 256) {
        int c = e >> 6, n = e & 63;
        float v = Hraw[((size_t)b * Cc + c) * Npix + n0 + n] * scale[c] + shift[c];
        S[c * BS_STRIDE + n] = v;
    }
    __syncthreads();
    {
        int n = tid & 63, part = tid >> 6;
        float p = 0.f;
        for (int c = part * 24; c < part * 24 + 24; c++) {
            float v = S[c * BS_STRIDE + n];
            p += v * v;
        }
        R[tid] = p;
    }
    __syncthreads();
    if (tid < 64) {
        float ssum = R[tid] + R[tid + 64] + R[tid + 128] + R[tid + 192];
        float rn = 1.0f / fmaxf(sqrtf(ssum), 1e-12f);
        Sq[(size_t)b * Npix + n0 + tid] = ssum * rn * rn;
        RN[tid] = rn;
    }
    __syncthreads();
    for (int e = tid; e < Cc * 64; e += 256) {
        int n = e / Cc, c = e - Cc * n;
        float v = S[c * BS_STRIDE + n];
        size_t o = ((size_t)b * Npix + n0 + n) * Cc + c;
        Ht[o] = v;
        Xnt[o] = v * RN[n];
    }
}

// ---------------- fused similarity GEMM (tf32 split mma, fragment-packed smem) + top-9 ----------------
// APH/APL: [kc][rs][gid][tg] float4(a0,a1,a2,a3)   -> 12*4*8*4 = 1536 float4 each
// BP:      [kc][col][tg]     float4(bh0,bh1,bl0,bl1)-> 12*64*4 = 3072 float4
#define SM_APH 0
#define SM_APL 6144
#define SM_BP  12288
#define SM_SQ  24576
#define KNN_SMEM_FLOATS 24640
#define KNN_SMEM_BYTES (KNN_SMEM_FLOATS*4)
#define MRG 73

__device__ __forceinline__ void mma_tf32(float* c, unsigned a0, unsigned a1, unsigned a2, unsigned a3,
                                         unsigned b0, unsigned b1) {
    asm volatile(
        "mma.sync.aligned.m16n8k8.row.col.f32.tf32.tf32.f32 "
        "{%0,%1,%2,%3}, {%4,%5,%6,%7}, {%8,%9}, {%0,%1,%2,%3};\n"
        : "+f"(c[0]), "+f"(c[1]), "+f"(c[2]), "+f"(c[3])
        : "r"(a0), "r"(a1), "r"(a2), "r"(a3), "r"(b0), "r"(b1));
}

__device__ __forceinline__ void topk_ins(float (&tv)[9], int (&ti)[9], float s, int m) {
    if (s > tv[8]) {
        tv[8] = s; ti[8] = m;
        #pragma unroll
        for (int p = 8; p > 0; p--) {
            if (tv[p] > tv[p - 1]) {
                float f = tv[p]; tv[p] = tv[p - 1]; tv[p - 1] = f;
                int i = ti[p]; ti[p] = ti[p - 1]; ti[p - 1] = i;
            }
        }
    }
}

__global__ __launch_bounds__(256, 2) void knn_kernel(
    const float* __restrict__ Xnt, const float* __restrict__ Sq,
    float* __restrict__ Val2, int* __restrict__ Idx2)
{
    extern __shared__ float sm[];
    const float4* APH4 = (const float4*)(sm + SM_APH);
    const float4* APL4 = (const float4*)(sm + SM_APL);
    const float4* BP4  = (const float4*)(sm + SM_BP);
    float* SqS = sm + SM_SQ;

    int tid = threadIdx.x;
    int warp = tid >> 5, lane = tid & 31;
    int gid = lane >> 2, tg = lane & 3;
    int rs = warp & 3;            // row strip (16 rows)
    int rbase = rs * 16;
    int ch = warp >> 2;           // candidate-column half (0/1)
    int b = blockIdx.z;
    int split = blockIdx.y;
    int row0 = blockIdx.x * 64;
    int t0 = split ? 25 : 0;
    int tc = split ? 24 : 25;

    const float* XB = Xnt + (size_t)b * Npix * Cc;

    // stage A tile (resident): convert fp32 -> hi/lo once, scatter into fragment order
    {
        const float4* g = (const float4*)(XB + (size_t)row0 * Cc);
        for (int f = tid; f < 64 * 24; f += 256) {
            int r = f / 24, k4 = f - r * 24;
            float4 v = g[f];
            int ars = r >> 4, agi = r & 7, arh = (r >> 3) & 1;
            #pragma unroll
            for (int e = 0; e < 4; e++) {
                float x = (&v.x)[e];
                float hi = __uint_as_float(__float_as_uint(x) & 0xFFFFE000u);
                float lo = x - hi;
                int k = k4 * 4 + e;
                int kc = k >> 3, ktg = k & 3, kh = (k >> 2) & 1;
                int fi = ((((kc * 4 + ars) * 8 + agi) * 4 + ktg) << 2) + kh * 2 + arh;
                sm[SM_APH + fi] = hi;
                sm[SM_APL + fi] = lo;
            }
        }
    }

    float tvA[KK], tvB[KK]; int tiA[KK], tiB[KK];
    #pragma unroll
    for (int q = 0; q < KK; q++) { tvA[q] = -1e30f; tvB[q] = -1e30f; tiA[q] = 0; tiB[q] = 0; }

    for (int t = t0; t < t0 + tc; t++) {
        int m0 = t * 64;
        __syncthreads();
        {
            const float4* g = (const float4*)(XB + (size_t)m0 * Cc);
            for (int f = tid; f < 64 * 24; f += 256) {
                int col = f / 24, k4 = f - col * 24;
                float4 v = g[f];
                #pragma unroll
                for (int e = 0; e < 4; e++) {
                    float x = (&v.x)[e];
                    float hi = __uint_as_float(__float_as_uint(x) & 0xFFFFE000u);
                    float lo = x - hi;
                    int k = k4 * 4 + e;
                    int kc = k >> 3, ktg = k & 3, kh = (k >> 2) & 1;
                    int fi = (((kc * 64 + col) * 4 + ktg) << 2);
                    sm[SM_BP + fi + kh]     = hi;
                    sm[SM_BP + fi + 2 + kh] = lo;
                }
            }
            if (tid < 64) SqS[tid] = Sq[(size_t)b * Npix + m0 + tid];
        }
        __syncthreads();

        float ach[4][4], acx[4][4];
        #pragma unroll
        for (int nt = 0; nt < 4; nt++)
            #pragma unroll
            for (int j = 0; j < 4; j++) { ach[nt][j] = 0.f; acx[nt][j] = 0.f; }

        #pragma unroll
        for (int kc = 0; kc < 12; kc++) {
            int ai = ((kc * 4 + rs) * 8 + gid) * 4 + tg;
            float4 AH = APH4[ai];
            float4 AL = APL4[ai];
            unsigned ah0 = __float_as_uint(AH.x), ah1 = __float_as_uint(AH.y);
            unsigned ah2 = __float_as_uint(AH.z), ah3 = __float_as_uint(AH.w);
            unsigned al0 = __float_as_uint(AL.x), al1 = __float_as_uint(AL.y);
            unsigned al2 = __float_as_uint(AL.z), al3 = __float_as_uint(AL.w);
            #pragma unroll
            for (int nt = 0; nt < 4; nt++) {
                float4 Bv = BP4[(kc * 64 + ch * 32 + nt * 8 + gid) * 4 + tg];
                unsigned bh0 = __float_as_uint(Bv.x), bh1 = __float_as_uint(Bv.y);
                unsigned bl0 = __float_as_uint(Bv.z), bl1 = __float_as_uint(Bv.w);
                mma_tf32(ach[nt], ah0, ah1, ah2, ah3, bh0, bh1);
                mma_tf32(acx[nt], ah0, ah1, ah2, ah3, bl0, bl1);
                mma_tf32(acx[nt], al0, al1, al2, al3, bh0, bh1);
            }
        }

        // scores + in-register top-9 (rows rbase+gid and rbase+gid+8)
        #pragma unroll
        for (int nt = 0; nt < 4; nt++) {
            int c = ch * 32 + nt * 8 + 2 * tg;
            float sq0 = SqS[c];
            float sq1 = SqS[c + 1];
            int m = m0 + c;
            float s0 = fmaf(2.f, ach[nt][0] + acx[nt][0], -sq0);
            float s1 = fmaf(2.f, ach[nt][1] + acx[nt][1], -sq1);
            float s2 = fmaf(2.f, ach[nt][2] + acx[nt][2], -sq0);
            float s3 = fmaf(2.f, ach[nt][3] + acx[nt][3], -sq1);
            topk_ins(tvA, tiA, s0, m);
            topk_ins(tvA, tiA, s1, m + 1);
            topk_ins(tvB, tiB, s2, m);
            topk_ins(tvB, tiB, s3, m + 1);
        }
    }
    __syncthreads();

    // merge 8 per-row lists (4 lanes x 2 col-halves); alias over tile regions
    float* mv = sm;                      // [64][MRG] (72 used)
    int*   mi = (int*)(sm + 64 * MRG);   // [64][MRG]
    int list = ch * 4 + tg;
    int la = rbase + gid;
    #pragma unroll
    for (int q = 0; q < KK; q++) {
        mv[la * MRG + list * KK + q] = tvA[q];
        mi[la * MRG + list * KK + q] = tiA[q];
        mv[(la + 8) * MRG + list * KK + q] = tvB[q];
        mi[(la + 8) * MRG + list * KK + q] = tiB[q];
    }
    __syncthreads();
    if (tid < 64) {
        float* crow = &mv[tid * MRG];
        int*   irow = &mi[tid * MRG];
        size_t base = ((size_t)(b * 2 + split) * Npix + row0 + tid) * KK;
        #pragma unroll
        for (int q = 0; q < KK; q++) {
            float best = -3.0e38f; int bi = 0x7fffffff, bj = 0;
            for (int j = 0; j < 72; j++) {
                float v = crow[j]; int id = irow[j];
                if (v > best || (v == best && id < bi)) { best = v; bi = id; bj = j; }
            }
            Val2[base + q] = best;
            Idx2[base + q] = bi;
            crow[bj] = -3.0e38f;
            irow[bj] = 0x7fffffff;
        }
    }
}

// ---------------- cross-split merge ----------------
__global__ __launch_bounds__(256) void knn_merge_kernel(
    const float* __restrict__ Val2, const int* __restrict__ Idx2, int* __restrict__ Idx)
{
    int i = blockIdx.x * 256 + threadIdx.x;
    if (i >= Bn * Npix) return;
    int b = i / Npix, n = i - b * Npix;
    size_t ba = ((size_t)(b * 2) * Npix + n) * KK;
    size_t bb = ((size_t)(b * 2 + 1) * Npix + n) * KK;
    int* o = Idx + ((size_t)b * Npix + n) * KK;
    int p = 0, q = 0;
    #pragma unroll
    for (int k = 0; k < KK; k++) {
        bool takeA;
        if (p >= KK) takeA = false;
        else if (q >= KK) takeA = true;
        else {
            float fa = Val2[ba + p], fb = Val2[bb + q];
            int xa = Idx2[ba + p], xb = Idx2[bb + q];
            takeA = (fa > fb) || (fa == fb && xa < xb);
        }
        o[k] = takeA ? Idx2[ba + p++] : Idx2[bb + q++];
    }
}

// ---------------- gather + max-relative + interleave ----------------
__global__ __launch_bounds__(256) void build_y_kernel(
    const float* __restrict__ Ht, const int* __restrict__ Idx, float* __restrict__ Y)
{
    __shared__ int sidx[32 * KK];
    __shared__ float T[C2 * 33];
    int tid = threadIdx.x;
    int b = blockIdx.y;
    int n0 = blockIdx.x * 32;
    const float* hb = Ht + (size_t)b * Npix * Cc;

    for (int e = tid; e < 32 * KK; e += 256)
        sidx[e] = Idx[((size_t)b * Npix + n0) * KK + e];
    __syncthreads();

    int nl = tid >> 3, part = tid & 7;
    int c0 = part * 12;
    const float4* hr = (const float4*)(hb + (size_t)(n0 + nl) * Cc + c0);
    float4 v0 = hr[0], v1 = hr[1], v2 = hr[2];
    float v[12] = {v0.x, v0.y, v0.z, v0.w, v1.x, v1.y, v1.z, v1.w, v2.x, v2.y, v2.z, v2.w};
    float mx[12];
    #pragma unroll
    for (int j = 0; j < 12; j++) mx[j] = -1e30f;
    #pragma unroll
    for (int k = 0; k < KK; k++) {
        const float4* hn = (const float4*)(hb + (size_t)sidx[nl * KK + k] * Cc + c0);
        float4 a = hn[0], c = hn[1], d = hn[2];
        float w[12] = {a.x, a.y, a.z, a.w, c.x, c.y, c.z, c.w, d.x, d.y, d.z, d.w};
        #pragma unroll
        for (int j = 0; j < 12; j++) mx[j] = fmaxf(mx[j], w[j]);
    }
    #pragma unroll
    for (int j = 0; j < 12; j++) {
        int c = c0 + j;
        T[(2 * c) * 33 + nl]     = v[j];
        T[(2 * c + 1) * 33 + nl] = mx[j] - v[j];
    }
    __syncthreads();
    float* yb = Y + (size_t)b * C2 * Npix;
    for (int e = tid; e < C2 * 32; e += 256) {
        int r = e >> 5, n = e & 31;
        yb[(size_t)r * Npix + n0 + n] = T[r * 33 + n];
    }
}

// ---------------- BN apply + exact GELU (float4) ----------------
__global__ __launch_bounds__(256) void bn_act_kernel(
    float* __restrict__ X, const float* __restrict__ scale, const float* __restrict__ shift, int C)
{
    size_t i = (size_t)blockIdx.x * 256 + threadIdx.x;
    int c = (int)((i * 4 / Npix) % C);
    float sc = scale[c], sh = shift[c];
    float4 v = ((float4*)X)[i];
    float a[4] = {v.x, v.y, v.z, v.w};
    #pragma unroll
    for (int j = 0; j < 4; j++) {
        float t = a[j] * sc + sh;
        a[j] = 0.5f * t * (1.0f + erff(t * 0.70710678118654752f));
    }
    ((float4*)X)[i] = make_float4(a[0], a[1], a[2], a[3]);
}

// ---------------- final BN + residual (float4) ----------------
__global__ __launch_bounds__(256) void bn_res_out_kernel(
    const float* __restrict__ raw, const float* __restrict__ scale, const float* __restrict__ shift,
    const float* __restrict__ x, float* __restrict__ out)
{
    size_t i = (size_t)blockIdx.x * 256 + threadIdx.x;
    int c = (int)((i * 4 / Npix) % Cc);
    float sc = scale[c], sh = shift[c];
    float4 r = ((const float4*)raw)[i];
    float4 xv = ((const float4*)x)[i];
    float4 o;
    o.x = r.x * sc + sh + xv.x;
    o.y = r.y * sc + sh + xv.y;
    o.z = r.z * sc + sh + xv.z;
    o.w = r.w * sc + sh + xv.w;
    ((float4*)out)[i] = o;
}

// ---------------- launch ----------------
extern "C" void kernel_launch(void* const* d_in, const int* in_sizes, int n_in,
                              void* d_out, int out_size)
{
    const float* x      = (const float*)d_in[0];
    const float* fc1_w  = (const float*)d_in[1];
    const float* fc1_g  = (const float*)d_in[3];
    const float* fc1_be = (const float*)d_in[4];
    const float* g1_w   = (const float*)d_in[5];
    const float* g1_g   = (const float*)d_in[7];
    const float* g1_be  = (const float*)d_in[8];
    const float* g2_w   = (const float*)d_in[9];
    const float* g2_g   = (const float*)d_in[11];
    const float* g2_be  = (const float*)d_in[12];
    const float* fc2_w  = (const float*)d_in[13];
    const float* fc2_g  = (const float*)d_in[15];
    const float* fc2_be = (const float*)d_in[16];

    float *h, *ht, *xnt, *sq, *y, *t1, *ps, *pss, *scale, *shift, *val2;
    int *idx, *idx2;
    cudaGetSymbolAddress((void**)&h,     g_h);
    cudaGetSymbolAddress((void**)&ht,    g_ht);
    cudaGetSymbolAddress((void**)&xnt,   g_xnt);
    cudaGetSymbolAddress((void**)&sq,    g_sq);
    cudaGetSymbolAddress((void**)&idx,   g_idx);
    cudaGetSymbolAddress((void**)&val2,  g_val2);
    cudaGetSymbolAddress((void**)&idx2,  g_idx2);
    cudaGetSymbolAddress((void**)&y,     g_y);
    cudaGetSymbolAddress((void**)&t1,    g_t1);
    cudaGetSymbolAddress((void**)&ps,    g_ps);
    cudaGetSymbolAddress((void**)&pss,   g_pss);
    cudaGetSymbolAddress((void**)&scale, g_scale);
    cudaGetSymbolAddress((void**)&shift, g_shift);

    cudaFuncSetAttribute(knn_kernel, cudaFuncAttributeMaxDynamicSharedMemorySize, KNN_SMEM_BYTES);

    // fc1 (bias dropped: cancels in BN)
    sgemm_bn_kernel<<<dim3(NB_N, 1, Bn), 256>>>(fc1_w, x, h, ps, pss, Cc, Cc);
    bn_finalize_kernel<<<1, 256>>>(ps, pss, fc1_g, fc1_be, scale, shift, Cc);
    bn_norm_kernel<<<dim3(Npix / 64, Bn), 256>>>(h, scale, shift, ht, xnt, sq);

    // knn (tf32 split mma, fragment-packed smem) + cross-split merge
    knn_kernel<<<dim3(Npix / 64, 2, Bn), 256, KNN_SMEM_BYTES>>>(xnt, sq, val2, idx2);
    knn_merge_kernel<<<(Bn * Npix + 255) / 256, 256>>>(val2, idx2, idx);

    // gather + interleave
    build_y_kernel<<<dim3(Npix / 32, Bn), 256>>>(ht, idx, y);

    // g1
    sgemm_bn_kernel<<<dim3(NB_N, 2, Bn), 256>>>(g1_w, y, t1, ps, pss, C2, C2);
    bn_finalize_kernel<<<1, 256>>>(ps, pss, g1_g, g1_be, scale, shift, C2);
    bn_act_kernel<<<(Bn * C2 * Npix) / 1024, 256>>>(t1, scale, shift, C2);

    // g2
    sgemm_bn_kernel<<<dim3(NB_N, 2, Bn), 256>>>(g2_w, t1, y, ps, pss, C2, C2);
    bn_finalize_kernel<<<1, 256>>>(ps, pss, g2_g, g2_be, scale, shift, C2);
    bn_act_kernel<<<(Bn * C2 * Npix) / 1024, 256>>>(y, scale, shift, C2);

    // fc2
    sgemm_bn_kernel<<<dim3(NB_N, 1, Bn), 256>>>(fc2_w, y, h, ps, pss, Cc, C2);
    bn_finalize_kernel<<<1, 256>>>(ps, pss, fc2_g, fc2_be, scale, shift, Cc);
    bn_res_out_kernel<<<(Bn * Cc * Npix) / 1024, 256>>>(h, scale, shift, x, (float*)d_out);
}

// round 10
// speedup vs baseline: 1.3872x; 1.3872x over previous
#include <cuda_runtime.h>
#include <math.h>

#define Bn 8
#define Cc 96
#define C2 192
#define Npix 3136
#define KK 9
#define BNtot 25088       // Bn*Npix
#define NSPLIT 3
#define PSG 392           // 8 batches * 49 n-blocks

// ---------------- scratch ----------------
__device__ float g_h  [Bn*Cc*Npix];
__device__ float g_ht [Bn*Npix*Cc];
__device__ float g_xnt[Bn*Npix*Cc];     // L2-normalized features, (B,N,C)
__device__ float g_sq [Bn*Npix];
__device__ int   g_idx[Bn*Npix*KK];
__device__ float g_val2[Bn*NSPLIT*Npix*KK];
__device__ int   g_idx2[Bn*NSPLIT*Npix*KK];
__device__ float g_y  [Bn*C2*Npix];
__device__ float g_t1 [Bn*C2*Npix];
__device__ float g_ps [C2*PSG];
__device__ float g_pss[C2*PSG];
__device__ float g_scale[C2];
__device__ float g_shift[C2];

// ---------------- shared helpers ----------------
__device__ __forceinline__ void mma_tf32(float* c, unsigned a0, unsigned a1, unsigned a2, unsigned a3,
                                         unsigned b0, unsigned b1) {
    asm volatile(
        "mma.sync.aligned.m16n8k8.row.col.f32.tf32.tf32.f32 "
        "{%0,%1,%2,%3}, {%4,%5,%6,%7}, {%8,%9}, {%0,%1,%2,%3};\n"
        : "+f"(c[0]), "+f"(c[1]), "+f"(c[2]), "+f"(c[3])
        : "r"(a0), "r"(a1), "r"(a2), "r"(a3), "r"(b0), "r"(b1));
}

__device__ __forceinline__ unsigned hif(float f) {
    return __float_as_uint(f) & 0xFFFFE000u;
}
__device__ __forceinline__ unsigned lof(float f, unsigned h) {
    return __float_as_uint(f - __uint_as_float(h));
}

__device__ __forceinline__ void topk_ins(float (&tv)[9], int (&ti)[9], float s, int m) {
    if (s > tv[8]) {
        tv[8] = s; ti[8] = m;
        #pragma unroll
        for (int p = 8; p > 0; p--) {
            if (tv[p] > tv[p - 1]) {
                float f = tv[p]; tv[p] = tv[p - 1]; tv[p - 1] = f;
                int i = ti[p]; ti[p] = ti[p - 1]; ti[p - 1] = i;
            }
        }
    }
}

// ---------------- tf32 GEMM + fused BN partial stats (no bias: BN cancels it) ----------------
// Out[b,m,n] = sum_k W[m,k]*Act[b,k,n]; hi/lo split (3 MMA) => fp32-class accuracy.
// Block: 192 threads = 6 warps; warp = 16-row strip x 64 cols (8 n-tiles).
// Block tile: 96 rows x 64 cols; grid (49, M/96, Bn). 49*64 = 3136 exact.
#define TG_PAD 72

__global__ __launch_bounds__(192, 2) void gemm_bn_kernel(
    const float* __restrict__ W, const float* __restrict__ Act,
    float* __restrict__ Out, float* __restrict__ ps, float* __restrict__ pss,
    int M, int Kd)
{
    extern __shared__ float sg[];
    int KSTR = Kd + 4;               // pad: banks 4*gid+tg, conflict-free
    float* A_s = sg;                 // [96][KSTR]
    float* B_s = sg + 96 * KSTR;     // [32][TG_PAD]

    int tid = threadIdx.x;
    int warp = tid >> 5, lane = tid & 31;
    int gid = lane >> 2, tg = lane & 3;
    int b = blockIdx.z;
    int m0 = blockIdx.y * 96;
    int n0 = blockIdx.x * 64;
    int nb = blockIdx.x;

    // stage A = W[m0..m0+95][0..Kd) whole-K (resident)
    {
        int k4n = Kd >> 2;
        const float4* gw = (const float4*)(W + (size_t)m0 * Kd);
        for (int e = tid; e < 96 * k4n; e += 192) {
            int r = e / k4n, k4 = e - r * k4n;
            *(float4*)(A_s + r * KSTR + k4 * 4) = gw[e];
        }
    }

    float ach[8][4], acx[8][4];
    #pragma unroll
    for (int nt = 0; nt < 8; nt++)
        #pragma unroll
        for (int j = 0; j < 4; j++) { ach[nt][j] = 0.f; acx[nt][j] = 0.f; }

    int nch = Kd >> 5;
    for (int kch = 0; kch < nch; kch++) {
        __syncthreads();
        {
            const float* gb = Act + ((size_t)b * Kd + kch * 32) * Npix + n0;
            for (int e = tid; e < 32 * 16; e += 192) {
                int k = e >> 4, n4 = e & 15;
                *(float4*)(B_s + k * TG_PAD + n4 * 4) =
                    *(const float4*)(gb + (size_t)k * Npix + n4 * 4);
            }
        }
        __syncthreads();
        #pragma unroll
        for (int kc = 0; kc < 4; kc++) {
            int ra = (warp * 16 + gid) * KSTR + kch * 32 + kc * 8 + tg;
            float f0 = A_s[ra],     f1 = A_s[ra + 8 * KSTR];
            float f2 = A_s[ra + 4], f3 = A_s[ra + 8 * KSTR + 4];
            unsigned ah0 = hif(f0), ah1 = hif(f1), ah2 = hif(f2), ah3 = hif(f3);
            unsigned al0 = lof(f0, ah0), al1 = lof(f1, ah1), al2 = lof(f2, ah2), al3 = lof(f3, ah3);
            #pragma unroll
            for (int nt = 0; nt < 8; nt++) {
                int bb = (kc * 8 + tg) * TG_PAD + nt * 8 + gid;
                float g0 = B_s[bb], g1 = B_s[bb + 4 * TG_PAD];
                unsigned bh0 = hif(g0), bh1 = hif(g1);
                unsigned bl0 = lof(g0, bh0), bl1 = lof(g1, bh1);
                mma_tf32(ach[nt], ah0, ah1, ah2, ah3, bh0, bh1);
                mma_tf32(acx[nt], ah0, ah1, ah2, ah3, bl0, bl1);
                mma_tf32(acx[nt], al0, al1, al2, al3, bh0, bh1);
            }
        }
    }

    // epilogue: store + per-row BN partials
    int mrow = m0 + warp * 16 + gid;
    float* Crow  = Out + ((size_t)b * M + mrow) * Npix + n0;
    float* Crow8 = Crow + (size_t)8 * Npix;
    float s0 = 0.f, q0 = 0.f, s1 = 0.f, q1 = 0.f;
    #pragma unroll
    for (int nt = 0; nt < 8; nt++) {
        float c0 = ach[nt][0] + acx[nt][0], c1 = ach[nt][1] + acx[nt][1];
        float c2 = ach[nt][2] + acx[nt][2], c3 = ach[nt][3] + acx[nt][3];
        int col = nt * 8 + 2 * tg;
        *(float2*)(Crow + col)  = make_float2(c0, c1);
        *(float2*)(Crow8 + col) = make_float2(c2, c3);
        s0 += c0 + c1; q0 += c0 * c0 + c1 * c1;
        s1 += c2 + c3; q1 += c2 * c2 + c3 * c3;
    }
    #pragma unroll
    for (int off = 2; off > 0; off >>= 1) {
        s0 += __shfl_down_sync(0xffffffffu, s0, off, 4);
        q0 += __shfl_down_sync(0xffffffffu, q0, off, 4);
        s1 += __shfl_down_sync(0xffffffffu, s1, off, 4);
        q1 += __shfl_down_sync(0xffffffffu, q1, off, 4);
    }
    if (tg == 0) {
        size_t sl0 = (size_t)mrow * PSG + b * 49 + nb;
        size_t sl1 = (size_t)(mrow + 8) * PSG + b * 49 + nb;
        ps[sl0] = s0; pss[sl0] = q0;
        ps[sl1] = s1; pss[sl1] = q1;
    }
}

// ---------------- BN finalize ----------------
__global__ void bn_finalize_kernel(
    const float* __restrict__ ps, const float* __restrict__ pss,
    const float* __restrict__ g, const float* __restrict__ be,
    float* __restrict__ scale, float* __restrict__ shift, int C)
{
    int c = blockIdx.x * blockDim.x + threadIdx.x;
    if (c >= C) return;
    float s = 0.f, ss = 0.f;
    for (int i = 0; i < PSG; i++) { s += ps[(size_t)c * PSG + i]; ss += pss[(size_t)c * PSG + i]; }
    float mean = s * (1.0f / (float)BNtot);
    float var  = ss * (1.0f / (float)BNtot) - mean * mean;
    float inv  = rsqrtf(var + 1e-5f);
    float sc = g[c] * inv;
    scale[c] = sc;
    shift[c] = be[c] - mean * sc;
}

// ---------------- BN apply + transpose + L2 normalize ----------------
#define BS_STRIDE 67
__global__ __launch_bounds__(256) void bn_norm_kernel(
    const float* __restrict__ Hraw, const float* __restrict__ scale, const float* __restrict__ shift,
    float* __restrict__ Ht, float* __restrict__ Xnt, float* __restrict__ Sq)
{
    __shared__ float S[Cc * BS_STRIDE];
    __shared__ float R[256];
    __shared__ float RN[64];
    int tid = threadIdx.x;
    int b = blockIdx.y;
    int n0 = blockIdx.x * 64;

    for (int e = tid; e < Cc * 64; e += 256) {
        int c = e >> 6, n = e & 63;
        float v = Hraw[((size_t)b * Cc + c) * Npix + n0 + n] * scale[c] + shift[c];
        S[c * BS_STRIDE + n] = v;
    }
    __syncthreads();
    {
        int n = tid & 63, part = tid >> 6;
        float p = 0.f;
        for (int c = part * 24; c < part * 24 + 24; c++) {
            float v = S[c * BS_STRIDE + n];
            p += v * v;
        }
        R[tid] = p;
    }
    __syncthreads();
    if (tid < 64) {
        float ssum = R[tid] + R[tid + 64] + R[tid + 128] + R[tid + 192];
        float rn = 1.0f / fmaxf(sqrtf(ssum), 1e-12f);
        Sq[(size_t)b * Npix + n0 + tid] = ssum * rn * rn;
        RN[tid] = rn;
    }
    __syncthreads();
    for (int e = tid; e < Cc * 64; e += 256) {
        int n = e / Cc, c = e - Cc * n;
        float v = S[c * BS_STRIDE + n];
        size_t o = ((size_t)b * Npix + n0 + n) * Cc + c;
        Ht[o] = v;
        Xnt[o] = v * RN[n];
    }
}

// ---------------- fused similarity GEMM (tf32 split mma, round-7 structure) + top-9 ----------------
#define SAB 100
#define SM_B 6400
#define SM_SQ 12800
#define KNN_SMEM_FLOATS 12864
#define KNN_SMEM_BYTES (KNN_SMEM_FLOATS*4)
#define MRG 73

__global__ __launch_bounds__(256, 2) void knn_kernel(
    const float* __restrict__ Xnt, const float* __restrict__ Sq,
    float* __restrict__ Val2, int* __restrict__ Idx2)
{
    extern __shared__ float sm[];
    float* Atile = sm;            // [64][SAB] fp32
    float* Btile = sm + SM_B;     // [64][SAB] fp32
    float* SqS   = sm + SM_SQ;    // [64]

    int tid = threadIdx.x;
    int warp = tid >> 5, lane = tid & 31;
    int gid = lane >> 2, tg = lane & 3;
    int rbase = (warp & 3) * 16;  // row strip
    int ch = warp >> 2;           // candidate-column half (0/1)
    int b = blockIdx.z;
    int split = blockIdx.y;       // 0..2
    int row0 = blockIdx.x * 64;
    int t0 = (split == 0) ? 0 : (17 + 16 * (split - 1));
    int tc = (split == 0) ? 17 : 16;

    const float* XB = Xnt + (size_t)b * Npix * Cc;

    // stage A tile (resident): 64 rows x 96 fp32
    {
        const float4* g = (const float4*)(XB + (size_t)row0 * Cc);
        for (int f = tid; f < 64 * 24; f += 256) {
            int r = f / 24, k4 = f - r * 24;
            *(float4*)(Atile + r * SAB + k4 * 4) = g[r * 24 + k4];
        }
    }

    float tvA[KK], tvB[KK]; int tiA[KK], tiB[KK];
    #pragma unroll
    for (int q = 0; q < KK; q++) { tvA[q] = -1e30f; tvB[q] = -1e30f; tiA[q] = 0; tiB[q] = 0; }

    for (int t = t0; t < t0 + tc; t++) {
        int m0 = t * 64;
        __syncthreads();
        {
            const float4* g = (const float4*)(XB + (size_t)m0 * Cc);
            for (int f = tid; f < 64 * 24; f += 256) {
                int r = f / 24, k4 = f - r * 24;
                *(float4*)(Btile + r * SAB + k4 * 4) = g[r * 24 + k4];
            }
            if (tid < 64) SqS[tid] = Sq[(size_t)b * Npix + m0 + tid];
        }
        __syncthreads();

        float ach[4][4], acx[4][4];
        #pragma unroll
        for (int nt = 0; nt < 4; nt++)
            #pragma unroll
            for (int j = 0; j < 4; j++) { ach[nt][j] = 0.f; acx[nt][j] = 0.f; }

        #pragma unroll
        for (int kc = 0; kc < 12; kc++) {
            int k0 = kc * 8;
            int ra = (rbase + gid) * SAB + k0 + tg;
            float f0 = Atile[ra],     f1 = Atile[ra + 8 * SAB];
            float f2 = Atile[ra + 4], f3 = Atile[ra + 8 * SAB + 4];
            unsigned ah0 = hif(f0), ah1 = hif(f1), ah2 = hif(f2), ah3 = hif(f3);
            unsigned al0 = lof(f0, ah0), al1 = lof(f1, ah1), al2 = lof(f2, ah2), al3 = lof(f3, ah3);
            #pragma unroll
            for (int nt = 0; nt < 4; nt++) {
                int nb = (ch * 32 + nt * 8 + gid) * SAB + k0 + tg;
                float g0 = Btile[nb], g1 = Btile[nb + 4];
                unsigned bh0 = hif(g0), bh1 = hif(g1);
                unsigned bl0 = lof(g0, bh0), bl1 = lof(g1, bh1);
                mma_tf32(ach[nt], ah0, ah1, ah2, ah3, bh0, bh1);
                mma_tf32(acx[nt], ah0, ah1, ah2, ah3, bl0, bl1);
                mma_tf32(acx[nt], al0, al1, al2, al3, bh0, bh1);
            }
        }

        // scores + in-register top-9 (rows rbase+gid and rbase+gid+8)
        #pragma unroll
        for (int nt = 0; nt < 4; nt++) {
            int c = ch * 32 + nt * 8 + 2 * tg;
            float sq0 = SqS[c];
            float sq1 = SqS[c + 1];
            int m = m0 + c;
            float s0 = fmaf(2.f, ach[nt][0] + acx[nt][0], -sq0);
            float s1 = fmaf(2.f, ach[nt][1] + acx[nt][1], -sq1);
            float s2 = fmaf(2.f, ach[nt][2] + acx[nt][2], -sq0);
            float s3 = fmaf(2.f, ach[nt][3] + acx[nt][3], -sq1);
            topk_ins(tvA, tiA, s0, m);
            topk_ins(tvA, tiA, s1, m + 1);
            topk_ins(tvB, tiB, s2, m);
            topk_ins(tvB, tiB, s3, m + 1);
        }
    }
    __syncthreads();

    // merge 8 per-row lists (4 lanes x 2 col-halves); alias over tile regions
    float* mv = sm;                      // [64][MRG] (72 used)
    int*   mi = (int*)(sm + 64 * MRG);   // [64][MRG]
    int list = ch * 4 + tg;
    int la = rbase + gid;
    #pragma unroll
    for (int q = 0; q < KK; q++) {
        mv[la * MRG + list * KK + q] = tvA[q];
        mi[la * MRG + list * KK + q] = tiA[q];
        mv[(la + 8) * MRG + list * KK + q] = tvB[q];
        mi[(la + 8) * MRG + list * KK + q] = tiB[q];
    }
    __syncthreads();
    if (tid < 64) {
        float* crow = &mv[tid * MRG];
        int*   irow = &mi[tid * MRG];
        size_t base = ((size_t)(b * NSPLIT + split) * Npix + row0 + tid) * KK;
        #pragma unroll
        for (int q = 0; q < KK; q++) {
            float best = -3.0e38f; int bi = 0x7fffffff, bj = 0;
            for (int j = 0; j < 72; j++) {
                float v = crow[j]; int id = irow[j];
                if (v > best || (v == best && id < bi)) { best = v; bi = id; bj = j; }
            }
            Val2[base + q] = best;
            Idx2[base + q] = bi;
            crow[bj] = -3.0e38f;
            irow[bj] = 0x7fffffff;
        }
    }
}

// ---------------- cross-split merge (3-way) ----------------
__global__ __launch_bounds__(256) void knn_merge_kernel(
    const float* __restrict__ Val2, const int* __restrict__ Idx2, int* __restrict__ Idx)
{
    int i = blockIdx.x * 256 + threadIdx.x;
    if (i >= Bn * Npix) return;
    int b = i / Npix, n = i - b * Npix;
    size_t base[NSPLIT];
    int p[NSPLIT];
    #pragma unroll
    for (int s = 0; s < NSPLIT; s++) {
        base[s] = ((size_t)(b * NSPLIT + s) * Npix + n) * KK;
        p[s] = 0;
    }
    int* o = Idx + ((size_t)b * Npix + n) * KK;
    #pragma unroll
    for (int k = 0; k < KK; k++) {
        float bv = -3.0e38f; int bi = 0x7fffffff, bs = 0;
        #pragma unroll
        for (int s = 0; s < NSPLIT; s++) {
            if (p[s] < KK) {
                float v = Val2[base[s] + p[s]];
                int id = Idx2[base[s] + p[s]];
                if (v > bv || (v == bv && id < bi)) { bv = v; bi = id; bs = s; }
            }
        }
        o[k] = bi;
        p[bs]++;
    }
}

// ---------------- gather + max-relative + interleave ----------------
__global__ __launch_bounds__(256) void build_y_kernel(
    const float* __restrict__ Ht, const int* __restrict__ Idx, float* __restrict__ Y)
{
    __shared__ int sidx[32 * KK];
    __shared__ float T[C2 * 33];
    int tid = threadIdx.x;
    int b = blockIdx.y;
    int n0 = blockIdx.x * 32;
    const float* hb = Ht + (size_t)b * Npix * Cc;

    for (int e = tid; e < 32 * KK; e += 256)
        sidx[e] = Idx[((size_t)b * Npix + n0) * KK + e];
    __syncthreads();

    int nl = tid >> 3, part = tid & 7;
    int c0 = part * 12;
    const float4* hr = (const float4*)(hb + (size_t)(n0 + nl) * Cc + c0);
    float4 v0 = hr[0], v1 = hr[1], v2 = hr[2];
    float v[12] = {v0.x, v0.y, v0.z, v0.w, v1.x, v1.y, v1.z, v1.w, v2.x, v2.y, v2.z, v2.w};
    float mx[12];
    #pragma unroll
    for (int j = 0; j < 12; j++) mx[j] = -1e30f;
    #pragma unroll
    for (int k = 0; k < KK; k++) {
        const float4* hn = (const float4*)(hb + (size_t)sidx[nl * KK + k] * Cc + c0);
        float4 a = hn[0], c = hn[1], d = hn[2];
        float w[12] = {a.x, a.y, a.z, a.w, c.x, c.y, c.z, c.w, d.x, d.y, d.z, d.w};
        #pragma unroll
        for (int j = 0; j < 12; j++) mx[j] = fmaxf(mx[j], w[j]);
    }
    #pragma unroll
    for (int j = 0; j < 12; j++) {
        int c = c0 + j;
        T[(2 * c) * 33 + nl]     = v[j];
        T[(2 * c + 1) * 33 + nl] = mx[j] - v[j];
    }
    __syncthreads();
    float* yb = Y + (size_t)b * C2 * Npix;
    for (int e = tid; e < C2 * 32; e += 256) {
        int r = e >> 5, n = e & 31;
        yb[(size_t)r * Npix + n0 + n] = T[r * 33 + n];
    }
}

// ---------------- BN apply + exact GELU (float4) ----------------
__global__ __launch_bounds__(256) void bn_act_kernel(
    float* __restrict__ X, const float* __restrict__ scale, const float* __restrict__ shift, int C)
{
    size_t i = (size_t)blockIdx.x * 256 + threadIdx.x;
    int c = (int)((i * 4 / Npix) % C);
    float sc = scale[c], sh = shift[c];
    float4 v = ((float4*)X)[i];
    float a[4] = {v.x, v.y, v.z, v.w};
    #pragma unroll
    for (int j = 0; j < 4; j++) {
        float t = a[j] * sc + sh;
        a[j] = 0.5f * t * (1.0f + erff(t * 0.70710678118654752f));
    }
    ((float4*)X)[i] = make_float4(a[0], a[1], a[2], a[3]);
}

// ---------------- final BN + residual (float4) ----------------
__global__ __launch_bounds__(256) void bn_res_out_kernel(
    const float* __restrict__ raw, const float* __restrict__ scale, const float* __restrict__ shift,
    const float* __restrict__ x, float* __restrict__ out)
{
    size_t i = (size_t)blockIdx.x * 256 + threadIdx.x;
    int c = (int)((i * 4 / Npix) % Cc);
    float sc = scale[c], sh = shift[c];
    float4 r = ((const float4*)raw)[i];
    float4 xv = ((const float4*)x)[i];
    float4 o;
    o.x = r.x * sc + sh + xv.x;
    o.y = r.y * sc + sh + xv.y;
    o.z = r.z * sc + sh + xv.z;
    o.w = r.w * sc + sh + xv.w;
    ((float4*)out)[i] = o;
}

// ---------------- launch ----------------
extern "C" void kernel_launch(void* const* d_in, const int* in_sizes, int n_in,
                              void* d_out, int out_size)
{
    const float* x      = (const float*)d_in[0];
    const float* fc1_w  = (const float*)d_in[1];
    const float* fc1_g  = (const float*)d_in[3];
    const float* fc1_be = (const float*)d_in[4];
    const float* g1_w   = (const float*)d_in[5];
    const float* g1_g   = (const float*)d_in[7];
    const float* g1_be  = (const float*)d_in[8];
    const float* g2_w   = (const float*)d_in[9];
    const float* g2_g   = (const float*)d_in[11];
    const float* g2_be  = (const float*)d_in[12];
    const float* fc2_w  = (const float*)d_in[13];
    const float* fc2_g  = (const float*)d_in[15];
    const float* fc2_be = (const float*)d_in[16];

    float *h, *ht, *xnt, *sq, *y, *t1, *ps, *pss, *scale, *shift, *val2;
    int *idx, *idx2;
    cudaGetSymbolAddress((void**)&h,     g_h);
    cudaGetSymbolAddress((void**)&ht,    g_ht);
    cudaGetSymbolAddress((void**)&xnt,   g_xnt);
    cudaGetSymbolAddress((void**)&sq,    g_sq);
    cudaGetSymbolAddress((void**)&idx,   g_idx);
    cudaGetSymbolAddress((void**)&val2,  g_val2);
    cudaGetSymbolAddress((void**)&idx2,  g_idx2);
    cudaGetSymbolAddress((void**)&y,     g_y);
    cudaGetSymbolAddress((void**)&t1,    g_t1);
    cudaGetSymbolAddress((void**)&ps,    g_ps);
    cudaGetSymbolAddress((void**)&pss,   g_pss);
    cudaGetSymbolAddress((void**)&scale, g_scale);
    cudaGetSymbolAddress((void**)&shift, g_shift);

    int gemm_smem96  = (96 * (Cc + 4) + 32 * TG_PAD) * 4;   // Kd=96
    int gemm_smem192 = (96 * (C2 + 4) + 32 * TG_PAD) * 4;   // Kd=192
    cudaFuncSetAttribute(knn_kernel, cudaFuncAttributeMaxDynamicSharedMemorySize, KNN_SMEM_BYTES);
    cudaFuncSetAttribute(gemm_bn_kernel, cudaFuncAttributeMaxDynamicSharedMemorySize, gemm_smem192);

    // fc1 (bias dropped: cancels in BN)
    gemm_bn_kernel<<<dim3(49, 1, Bn), 192, gemm_smem96>>>(fc1_w, x, h, ps, pss, Cc, Cc);
    bn_finalize_kernel<<<1, 256>>>(ps, pss, fc1_g, fc1_be, scale, shift, Cc);
    bn_norm_kernel<<<dim3(Npix / 64, Bn), 256>>>(h, scale, shift, ht, xnt, sq);

    // knn (tf32 split mma, 3 candidate splits) + cross-split merge
    knn_kernel<<<dim3(Npix / 64, NSPLIT, Bn), 256, KNN_SMEM_BYTES>>>(xnt, sq, val2, idx2);
    knn_merge_kernel<<<(Bn * Npix + 255) / 256, 256>>>(val2, idx2, idx);

    // gather + interleave
    build_y_kernel<<<dim3(Npix / 32, Bn), 256>>>(ht, idx, y);

    // g1
    gemm_bn_kernel<<<dim3(49, 2, Bn), 192, gemm_smem192>>>(g1_w, y, t1, ps, pss, C2, C2);
    bn_finalize_kernel<<<1, 256>>>(ps, pss, g1_g, g1_be, scale, shift, C2);
    bn_act_kernel<<<(Bn * C2 * Npix) / 1024, 256>>>(t1, scale, shift, C2);

    // g2
    gemm_bn_kernel<<<dim3(49, 2, Bn), 192, gemm_smem192>>>(g2_w, t1, y, ps, pss, C2, C2);
    bn_finalize_kernel<<<1, 256>>>(ps, pss, g2_g, g2_be, scale, shift, C2);
    bn_act_kernel<<<(Bn * C2 * Npix) / 1024, 256>>>(y, scale, shift, C2);

    // fc2
    gemm_bn_kernel<<<dim3(49, 1, Bn), 192, gemm_smem192>>>(fc2_w, y, h, ps, pss, Cc, C2);
    bn_finalize_kernel<<<1, 256>>>(ps, pss, fc2_g, fc2_be, scale, shift, Cc);
    bn_res_out_kernel<<<(Bn * Cc * Npix) / 1024, 256>>>(h, scale, shift, x, (float*)d_out);
}

// round 12
// speedup vs baseline: 1.3874x; 1.0001x over previous
#include <cuda_runtime.h>
#include <math.h>

#define Bn 8
#define Cc 96
#define C2 192
#define Npix 3136
#define KK 9
#define BNtot 25088       // Bn*Npix
#define NSPLIT 3
#define PSG 392           // 8 batches * 49 n-blocks

// ---------------- scratch ----------------
__device__ float g_h  [Bn*Cc*Npix];
__device__ float g_ht [Bn*Npix*Cc];
__device__ float g_xh [Bn*Npix*Cc];     // tf32-hi of normalized features, (B,N,C)
__device__ float g_xl [Bn*Npix*Cc];     // fp32 residual
__device__ float g_sq [Bn*Npix];
__device__ int   g_idx[Bn*Npix*KK];
__device__ float g_val2[Bn*NSPLIT*Npix*KK];
__device__ int   g_idx2[Bn*NSPLIT*Npix*KK];
__device__ float g_y  [Bn*C2*Npix];
__device__ float g_t1 [Bn*C2*Npix];
__device__ float g_ps [C2*PSG];
__device__ float g_pss[C2*PSG];
__device__ float g_scale[C2];
__device__ float g_shift[C2];

// ---------------- shared helpers ----------------
__device__ __forceinline__ void mma_tf32(float* c, unsigned a0, unsigned a1, unsigned a2, unsigned a3,
                                         unsigned b0, unsigned b1) {
    asm volatile(
        "mma.sync.aligned.m16n8k8.row.col.f32.tf32.tf32.f32 "
        "{%0,%1,%2,%3}, {%4,%5,%6,%7}, {%8,%9}, {%0,%1,%2,%3};\n"
        : "+f"(c[0]), "+f"(c[1]), "+f"(c[2]), "+f"(c[3])
        : "r"(a0), "r"(a1), "r"(a2), "r"(a3), "r"(b0), "r"(b1));
}

__device__ __forceinline__ unsigned hif(float f) {
    return __float_as_uint(f) & 0xFFFFE000u;
}
__device__ __forceinline__ unsigned lof(float f, unsigned h) {
    return __float_as_uint(f - __uint_as_float(h));
}

__device__ __forceinline__ void topk_ins(float (&tv)[9], int (&ti)[9], float s, int m) {
    if (s > tv[8]) {
        tv[8] = s; ti[8] = m;
        #pragma unroll
        for (int p = 8; p > 0; p--) {
            if (tv[p] > tv[p - 1]) {
                float f = tv[p]; tv[p] = tv[p - 1]; tv[p - 1] = f;
                int i = ti[p]; ti[p] = ti[p - 1]; ti[p - 1] = i;
            }
        }
    }
}

// ---------------- tf32 GEMM + fused BN partial stats (no bias: BN cancels it) ----------------
#define TG_PAD 72

__global__ __launch_bounds__(192, 2) void gemm_bn_kernel(
    const float* __restrict__ W, const float* __restrict__ Act,
    float* __restrict__ Out, float* __restrict__ ps, float* __restrict__ pss,
    int M, int Kd)
{
    extern __shared__ float sg[];
    int KSTR = Kd + 4;               // pad: banks 4*gid+tg, conflict-free
    float* A_s = sg;                 // [96][KSTR]
    float* B_s = sg + 96 * KSTR;     // [32][TG_PAD]

    int tid = threadIdx.x;
    int warp = tid >> 5, lane = tid & 31;
    int gid = lane >> 2, tg = lane & 3;
    int b = blockIdx.z;
    int m0 = blockIdx.y * 96;
    int n0 = blockIdx.x * 64;
    int nb = blockIdx.x;

    // stage A = W[m0..m0+95][0..Kd) whole-K (resident)
    {
        int k4n = Kd >> 2;
        const float4* gw = (const float4*)(W + (size_t)m0 * Kd);
        for (int e = tid; e < 96 * k4n; e += 192) {
            int r = e / k4n, k4 = e - r * k4n;
            *(float4*)(A_s + r * KSTR + k4 * 4) = gw[e];
        }
    }

    float ach[8][4], acx[8][4];
    #pragma unroll
    for (int nt = 0; nt < 8; nt++)
        #pragma unroll
        for (int j = 0; j < 4; j++) { ach[nt][j] = 0.f; acx[nt][j] = 0.f; }

    int nch = Kd >> 5;
    for (int kch = 0; kch < nch; kch++) {
        __syncthreads();
        {
            const float* gb = Act + ((size_t)b * Kd + kch * 32) * Npix + n0;
            for (int e = tid; e < 32 * 16; e += 192) {
                int k = e >> 4, n4 = e & 15;
                *(float4*)(B_s + k * TG_PAD + n4 * 4) =
                    *(const float4*)(gb + (size_t)k * Npix + n4 * 4);
            }
        }
        __syncthreads();
        #pragma unroll
        for (int kc = 0; kc < 4; kc++) {
            int ra = (warp * 16 + gid) * KSTR + kch * 32 + kc * 8 + tg;
            float f0 = A_s[ra],     f1 = A_s[ra + 8 * KSTR];
            float f2 = A_s[ra + 4], f3 = A_s[ra + 8 * KSTR + 4];
            unsigned ah0 = hif(f0), ah1 = hif(f1), ah2 = hif(f2), ah3 = hif(f3);
            unsigned al0 = lof(f0, ah0), al1 = lof(f1, ah1), al2 = lof(f2, ah2), al3 = lof(f3, ah3);
            #pragma unroll
            for (int nt = 0; nt < 8; nt++) {
                int bb = (kc * 8 + tg) * TG_PAD + nt * 8 + gid;
                float g0 = B_s[bb], g1 = B_s[bb + 4 * TG_PAD];
                unsigned bh0 = hif(g0), bh1 = hif(g1);
                unsigned bl0 = lof(g0, bh0), bl1 = lof(g1, bh1);
                mma_tf32(ach[nt], ah0, ah1, ah2, ah3, bh0, bh1);
                mma_tf32(acx[nt], ah0, ah1, ah2, ah3, bl0, bl1);
                mma_tf32(acx[nt], al0, al1, al2, al3, bh0, bh1);
            }
        }
    }

    // epilogue: store + per-row BN partials
    int mrow = m0 + warp * 16 + gid;
    float* Crow  = Out + ((size_t)b * M + mrow) * Npix + n0;
    float* Crow8 = Crow + (size_t)8 * Npix;
    float s0 = 0.f, q0 = 0.f, s1 = 0.f, q1 = 0.f;
    #pragma unroll
    for (int nt = 0; nt < 8; nt++) {
        float c0 = ach[nt][0] + acx[nt][0], c1 = ach[nt][1] + acx[nt][1];
        float c2 = ach[nt][2] + acx[nt][2], c3 = ach[nt][3] + acx[nt][3];
        int col = nt * 8 + 2 * tg;
        *(float2*)(Crow + col)  = make_float2(c0, c1);
        *(float2*)(Crow8 + col) = make_float2(c2, c3);
        s0 += c0 + c1; q0 += c0 * c0 + c1 * c1;
        s1 += c2 + c3; q1 += c2 * c2 + c3 * c3;
    }
    #pragma unroll
    for (int off = 2; off > 0; off >>= 1) {
        s0 += __shfl_down_sync(0xffffffffu, s0, off, 4);
        q0 += __shfl_down_sync(0xffffffffu, q0, off, 4);
        s1 += __shfl_down_sync(0xffffffffu, s1, off, 4);
        q1 += __shfl_down_sync(0xffffffffu, q1, off, 4);
    }
    if (tg == 0) {
        size_t sl0 = (size_t)mrow * PSG + b * 49 + nb;
        size_t sl1 = (size_t)(mrow + 8) * PSG + b * 49 + nb;
        ps[sl0] = s0; pss[sl0] = q0;
        ps[sl1] = s1; pss[sl1] = q1;
    }
}

// ---------------- BN finalize ----------------
__global__ void bn_finalize_kernel(
    const float* __restrict__ ps, const float* __restrict__ pss,
    const float* __restrict__ g, const float* __restrict__ be,
    float* __restrict__ scale, float* __restrict__ shift, int C)
{
    int c = blockIdx.x * blockDim.x + threadIdx.x;
    if (c >= C) return;
    float s = 0.f, ss = 0.f;
    for (int i = 0; i < PSG; i++) { s += ps[(size_t)c * PSG + i]; ss += pss[(size_t)c * PSG + i]; }
    float mean = s * (1.0f / (float)BNtot);
    float var  = ss * (1.0f / (float)BNtot) - mean * mean;
    float inv  = rsqrtf(var + 1e-5f);
    float sc = g[c] * inv;
    scale[c] = sc;
    shift[c] = be[c] - mean * sc;
}

// ---------------- BN apply + transpose + L2 normalize + tf32 hi/lo split ----------------
#define BS_STRIDE 67
__global__ __launch_bounds__(256) void bn_norm_kernel(
    const float* __restrict__ Hraw, const float* __restrict__ scale, const float* __restrict__ shift,
    float* __restrict__ Ht, float* __restrict__ Xh, float* __restrict__ Xl, float* __restrict__ Sq)
{
    __shared__ float S[Cc * BS_STRIDE];
    __shared__ float R[256];
    __shared__ float RN[64];
    int tid = threadIdx.x;
    int b = blockIdx.y;
    int n0 = blockIdx.x * 64;

    for (int e = tid; e < Cc * 64; e += 256) {
        int c = e >> 6, n = e & 63;
        float v = Hraw[((size_t)b * Cc + c) * Npix + n0 + n] * scale[c] + shift[c];
        S[c * BS_STRIDE + n] = v;
    }
    __syncthreads();
    {
        int n = tid & 63, part = tid >> 6;
        float p = 0.f;
        for (int c = part * 24; c < part * 24 + 24; c++) {
            float v = S[c * BS_STRIDE + n];
            p += v * v;
        }
        R[tid] = p;
    }
    __syncthreads();
    if (tid < 64) {
        float ssum = R[tid] + R[tid + 64] + R[tid + 128] + R[tid + 192];
        float rn = 1.0f / fmaxf(sqrtf(ssum), 1e-12f);
        Sq[(size_t)b * Npix + n0 + tid] = ssum * rn * rn;
        RN[tid] = rn;
    }
    __syncthreads();
    for (int e = tid; e < Cc * 64; e += 256) {
        int n = e / Cc, c = e - Cc * n;
        float v = S[c * BS_STRIDE + n];
        size_t o = ((size_t)b * Npix + n0 + n) * Cc + c;
        Ht[o] = v;
        float xn = v * RN[n];
        float hi = __uint_as_float(__float_as_uint(xn) & 0xFFFFE000u);
        Xh[o] = hi;
        Xl[o] = xn - hi;
    }
}

// ---------------- fused similarity GEMM (tf32 split mma, precomputed hi/lo tiles) + top-9 ----------------
#define SAB 100
#define SM_AH 0
#define SM_AL 6400
#define SM_BH 12800
#define SM_BL 19200
#define SM_SQ 25600
#define KNN_SMEM_FLOATS 25664
#define KNN_SMEM_BYTES (KNN_SMEM_FLOATS*4)
#define MRG 73

__global__ __launch_bounds__(256, 2) void knn_kernel(
    const float* __restrict__ Xh, const float* __restrict__ Xl,
    const float* __restrict__ Sq, float* __restrict__ Val2, int* __restrict__ Idx2)
{
    extern __shared__ float sm[];
    const unsigned* uAH = (const unsigned*)(sm + SM_AH);
    const unsigned* uAL = (const unsigned*)(sm + SM_AL);
    const unsigned* uBH = (const unsigned*)(sm + SM_BH);
    const unsigned* uBL = (const unsigned*)(sm + SM_BL);
    float* SqS = sm + SM_SQ;

    int tid = threadIdx.x;
    int warp = tid >> 5, lane = tid & 31;
    int gid = lane >> 2, tg = lane & 3;
    int rbase = (warp & 3) * 16;  // row strip
    int ch = warp >> 2;           // candidate-column half (0/1)
    int b = blockIdx.z;
    int split = blockIdx.y;       // 0..2
    int row0 = blockIdx.x * 64;
    int t0 = (split == 0) ? 0 : (17 + 16 * (split - 1));
    int tc = (split == 0) ? 17 : 16;

    const float4* XhB = (const float4*)(Xh + (size_t)b * Npix * Cc);
    const float4* XlB = (const float4*)(Xl + (size_t)b * Npix * Cc);

    // stage A tiles (resident): straight float4 copies of precomputed hi/lo
    {
        int abase = row0 * 24;
        for (int f = tid; f < 64 * 24; f += 256) {
            int r = f / 24, k4 = f - r * 24;
            *(float4*)(sm + SM_AH + r * SAB + k4 * 4) = XhB[abase + f];
            *(float4*)(sm + SM_AL + r * SAB + k4 * 4) = XlB[abase + f];
        }
    }

    float tvA[KK], tvB[KK]; int tiA[KK], tiB[KK];
    #pragma unroll
    for (int q = 0; q < KK; q++) { tvA[q] = -1e30f; tvB[q] = -1e30f; tiA[q] = 0; tiB[q] = 0; }

    for (int t = t0; t < t0 + tc; t++) {
        int m0 = t * 64;
        __syncthreads();
        {
            int bbase = m0 * 24;
            for (int f = tid; f < 64 * 24; f += 256) {
                int r = f / 24, k4 = f - r * 24;
                *(float4*)(sm + SM_BH + r * SAB + k4 * 4) = XhB[bbase + f];
                *(float4*)(sm + SM_BL + r * SAB + k4 * 4) = XlB[bbase + f];
            }
            if (tid < 64) SqS[tid] = Sq[(size_t)b * Npix + m0 + tid];
        }
        __syncthreads();

        float ach[4][4], acx[4][4];
        #pragma unroll
        for (int nt = 0; nt < 4; nt++)
            #pragma unroll
            for (int j = 0; j < 4; j++) { ach[nt][j] = 0.f; acx[nt][j] = 0.f; }

        #pragma unroll
        for (int kc = 0; kc < 12; kc++) {
            int k0 = kc * 8;
            int ra = (rbase + gid) * SAB + k0 + tg;
            unsigned ah0 = uAH[ra],     ah1 = uAH[ra + 8 * SAB];
            unsigned ah2 = uAH[ra + 4], ah3 = uAH[ra + 8 * SAB + 4];
            unsigned al0 = uAL[ra],     al1 = uAL[ra + 8 * SAB];
            unsigned al2 = uAL[ra + 4], al3 = uAL[ra + 8 * SAB + 4];
            #pragma unroll
            for (int nt = 0; nt < 4; nt++) {
                int nb = (ch * 32 + nt * 8 + gid) * SAB + k0 + tg;
                unsigned bh0 = uBH[nb], bh1 = uBH[nb + 4];
                unsigned bl0 = uBL[nb], bl1 = uBL[nb + 4];
                // hl first, then independent hh, then lh: breaks the acx->acx
                // back-to-back chain while keeping per-accumulator order (hl, lh).
                mma_tf32(acx[nt], ah0, ah1, ah2, ah3, bl0, bl1);
                mma_tf32(ach[nt], ah0, ah1, ah2, ah3, bh0, bh1);
                mma_tf32(acx[nt], al0, al1, al2, al3, bh0, bh1);
            }
        }

        // scores + in-register top-9 (rows rbase+gid and rbase+gid+8)
        #pragma unroll
        for (int nt = 0; nt < 4; nt++) {
            int c = ch * 32 + nt * 8 + 2 * tg;
            float sq0 = SqS[c];
            float sq1 = SqS[c + 1];
            int m = m0 + c;
            float s0 = fmaf(2.f, ach[nt][0] + acx[nt][0], -sq0);
            float s1 = fmaf(2.f, ach[nt][1] + acx[nt][1], -sq1);
            float s2 = fmaf(2.f, ach[nt][2] + acx[nt][2], -sq0);
            float s3 = fmaf(2.f, ach[nt][3] + acx[nt][3], -sq1);
            topk_ins(tvA, tiA, s0, m);
            topk_ins(tvA, tiA, s1, m + 1);
            topk_ins(tvB, tiB, s2, m);
            topk_ins(tvB, tiB, s3, m + 1);
        }
    }
    __syncthreads();

    // merge 8 per-row lists (4 lanes x 2 col-halves); alias over tile regions
    float* mv = sm;                      // [64][MRG] (72 used)
    int*   mi = (int*)(sm + 64 * MRG);   // [64][MRG]
    int list = ch * 4 + tg;
    int la = rbase + gid;
    #pragma unroll
    for (int q = 0; q < KK; q++) {
        mv[la * MRG + list * KK + q] = tvA[q];
        mi[la * MRG + list * KK + q] = tiA[q];
        mv[(la + 8) * MRG + list * KK + q] = tvB[q];
        mi[(la + 8) * MRG + list * KK + q] = tiB[q];
    }
    __syncthreads();
    if (tid < 64) {
        float* crow = &mv[tid * MRG];
        int*   irow = &mi[tid * MRG];
        size_t base = ((size_t)(b * NSPLIT + split) * Npix + row0 + tid) * KK;
        #pragma unroll
        for (int q = 0; q < KK; q++) {
            float best = -3.0e38f; int bi = 0x7fffffff, bj = 0;
            for (int j = 0; j < 72; j++) {
                float v = crow[j]; int id = irow[j];
                if (v > best || (v == best && id < bi)) { best = v; bi = id; bj = j; }
            }
            Val2[base + q] = best;
            Idx2[base + q] = bi;
            crow[bj] = -3.0e38f;
            irow[bj] = 0x7fffffff;
        }
    }
}

// ---------------- cross-split merge (3-way) ----------------
__global__ __launch_bounds__(256) void knn_merge_kernel(
    const float* __restrict__ Val2, const int* __restrict__ Idx2, int* __restrict__ Idx)
{
    int i = blockIdx.x * 256 + threadIdx.x;
    if (i >= Bn * Npix) return;
    int b = i / Npix, n = i - b * Npix;
    size_t base[NSPLIT];
    int p[NSPLIT];
    #pragma unroll
    for (int s = 0; s < NSPLIT; s++) {
        base[s] = ((size_t)(b * NSPLIT + s) * Npix + n) * KK;
        p[s] = 0;
    }
    int* o = Idx + ((size_t)b * Npix + n) * KK;
    #pragma unroll
    for (int k = 0; k < KK; k++) {
        float bv = -3.0e38f; int bi = 0x7fffffff, bs = 0;
        #pragma unroll
        for (int s = 0; s < NSPLIT; s++) {
            if (p[s] < KK) {
                float v = Val2[base[s] + p[s]];
                int id = Idx2[base[s] + p[s]];
                if (v > bv || (v == bv && id < bi)) { bv = v; bi = id; bs = s; }
            }
        }
        o[k] = bi;
        p[bs]++;
    }
}

// ---------------- gather + max-relative + interleave ----------------
__global__ __launch_bounds__(256) void build_y_kernel(
    const float* __restrict__ Ht, const int* __restrict__ Idx, float* __restrict__ Y)
{
    __shared__ int sidx[32 * KK];
    __shared__ float T[C2 * 33];
    int tid = threadIdx.x;
    int b = blockIdx.y;
    int n0 = blockIdx.x * 32;
    const float* hb = Ht + (size_t)b * Npix * Cc;

    for (int e = tid; e < 32 * KK; e += 256)
        sidx[e] = Idx[((size_t)b * Npix + n0) * KK + e];
    __syncthreads();

    int nl = tid >> 3, part = tid & 7;
    int c0 = part * 12;
    const float4* hr = (const float4*)(hb + (size_t)(n0 + nl) * Cc + c0);
    float4 v0 = hr[0], v1 = hr[1], v2 = hr[2];
    float v[12] = {v0.x, v0.y, v0.z, v0.w, v1.x, v1.y, v1.z, v1.w, v2.x, v2.y, v2.z, v2.w};
    float mx[12];
    #pragma unroll
    for (int j = 0; j < 12; j++) mx[j] = -1e30f;
    #pragma unroll
    for (int k = 0; k < KK; k++) {
        const float4* hn = (const float4*)(hb + (size_t)sidx[nl * KK + k] * Cc + c0);
        float4 a = hn[0], c = hn[1], d = hn[2];
        float w[12] = {a.x, a.y, a.z, a.w, c.x, c.y, c.z, c.w, d.x, d.y, d.z, d.w};
        #pragma unroll
        for (int j = 0; j < 12; j++) mx[j] = fmaxf(mx[j], w[j]);
    }
    #pragma unroll
    for (int j = 0; j < 12; j++) {
        int c = c0 + j;
        T[(2 * c) * 33 + nl]     = v[j];
        T[(2 * c + 1) * 33 + nl] = mx[j] - v[j];
    }
    __syncthreads();
    float* yb = Y + (size_t)b * C2 * Npix;
    for (int e = tid; e < C2 * 32; e += 256) {
        int r = e >> 5, n = e & 31;
        yb[(size_t)r * Npix + n0 + n] = T[r * 33 + n];
    }
}

// ---------------- BN apply + exact GELU (float4) ----------------
__global__ __launch_bounds__(256) void bn_act_kernel(
    float* __restrict__ X, const float* __restrict__ scale, const float* __restrict__ shift, int C)
{
    size_t i = (size_t)blockIdx.x * 256 + threadIdx.x;
    int c = (int)((i * 4 / Npix) % C);
    float sc = scale[c], sh = shift[c];
    float4 v = ((float4*)X)[i];
    float a[4] = {v.x, v.y, v.z, v.w};
    #pragma unroll
    for (int j = 0; j < 4; j++) {
        float t = a[j] * sc + sh;
        a[j] = 0.5f * t * (1.0f + erff(t * 0.70710678118654752f));
    }
    ((float4*)X)[i] = make_float4(a[0], a[1], a[2], a[3]);
}

// ---------------- final BN + residual (float4) ----------------
__global__ __launch_bounds__(256) void bn_res_out_kernel(
    const float* __restrict__ raw, const float* __restrict__ scale, const float* __restrict__ shift,
    const float* __restrict__ x, float* __restrict__ out)
{
    size_t i = (size_t)blockIdx.x * 256 + threadIdx.x;
    int c = (int)((i * 4 / Npix) % Cc);
    float sc = scale[c], sh = shift[c];
    float4 r = ((const float4*)raw)[i];
    float4 xv = ((const float4*)x)[i];
    float4 o;
    o.x = r.x * sc + sh + xv.x;
    o.y = r.y * sc + sh + xv.y;
    o.z = r.z * sc + sh + xv.z;
    o.w = r.w * sc + sh + xv.w;
    ((float4*)out)[i] = o;
}

// ---------------- launch ----------------
extern "C" void kernel_launch(void* const* d_in, const int* in_sizes, int n_in,
                              void* d_out, int out_size)
{
    const float* x      = (const float*)d_in[0];
    const float* fc1_w  = (const float*)d_in[1];
    const float* fc1_g  = (const float*)d_in[3];
    const float* fc1_be = (const float*)d_in[4];
    const float* g1_w   = (const float*)d_in[5];
    const float* g1_g   = (const float*)d_in[7];
    const float* g1_be  = (const float*)d_in[8];
    const float* g2_w   = (const float*)d_in[9];
    const float* g2_g   = (const float*)d_in[11];
    const float* g2_be  = (const float*)d_in[12];
    const float* fc2_w  = (const float*)d_in[13];
    const float* fc2_g  = (const float*)d_in[15];
    const float* fc2_be = (const float*)d_in[16];

    float *h, *ht, *xh, *xl, *sq, *y, *t1, *ps, *pss, *scale, *shift, *val2;
    int *idx, *idx2;
    cudaGetSymbolAddress((void**)&h,     g_h);
    cudaGetSymbolAddress((void**)&ht,    g_ht);
    cudaGetSymbolAddress((void**)&xh,    g_xh);
    cudaGetSymbolAddress((void**)&xl,    g_xl);
    cudaGetSymbolAddress((void**)&sq,    g_sq);
    cudaGetSymbolAddress((void**)&idx,   g_idx);
    cudaGetSymbolAddress((void**)&val2,  g_val2);
    cudaGetSymbolAddress((void**)&idx2,  g_idx2);
    cudaGetSymbolAddress((void**)&y,     g_y);
    cudaGetSymbolAddress((void**)&t1,    g_t1);
    cudaGetSymbolAddress((void**)&ps,    g_ps);
    cudaGetSymbolAddress((void**)&pss,   g_pss);
    cudaGetSymbolAddress((void**)&scale, g_scale);
    cudaGetSymbolAddress((void**)&shift, g_shift);

    int gemm_smem96  = (96 * (Cc + 4) + 32 * TG_PAD) * 4;   // Kd=96
    int gemm_smem192 = (96 * (C2 + 4) + 32 * TG_PAD) * 4;   // Kd=192
    cudaFuncSetAttribute(knn_kernel, cudaFuncAttributeMaxDynamicSharedMemorySize, KNN_SMEM_BYTES);
    cudaFuncSetAttribute(gemm_bn_kernel, cudaFuncAttributeMaxDynamicSharedMemorySize, gemm_smem192);

    // fc1 (bias dropped: cancels in BN)
    gemm_bn_kernel<<<dim3(49, 1, Bn), 192, gemm_smem96>>>(fc1_w, x, h, ps, pss, Cc, Cc);
    bn_finalize_kernel<<<1, 256>>>(ps, pss, fc1_g, fc1_be, scale, shift, Cc);
    bn_norm_kernel<<<dim3(Npix / 64, Bn), 256>>>(h, scale, shift, ht, xh, xl, sq);

    // knn (tf32 split mma, precomputed hi/lo, 3 candidate splits) + merge
    knn_kernel<<<dim3(Npix / 64, NSPLIT, Bn), 256, KNN_SMEM_BYTES>>>(xh, xl, sq, val2, idx2);
    knn_merge_kernel<<<(Bn * Npix + 255) / 256, 256>>>(val2, idx2, idx);

    // gather + interleave
    build_y_kernel<<<dim3(Npix / 32, Bn), 256>>>(ht, idx, y);

    // g1
    gemm_bn_kernel<<<dim3(49, 2, Bn), 192, gemm_smem192>>>(g1_w, y, t1, ps, pss, C2, C2);
    bn_finalize_kernel<<<1, 256>>>(ps, pss, g1_g, g1_be, scale, shift, C2);
    bn_act_kernel<<<(Bn * C2 * Npix) / 1024, 256>>>(t1, scale, shift, C2);

    // g2
    gemm_bn_kernel<<<dim3(49, 2, Bn), 192, gemm_smem192>>>(g2_w, t1, y, ps, pss, C2, C2);
    bn_finalize_kernel<<<1, 256>>>(ps, pss, g2_g, g2_be, scale, shift, C2);
    bn_act_kernel<<<(Bn * C2 * Npix) / 1024, 256>>>(y, scale, shift, C2);

    // fc2
    gemm_bn_kernel<<<dim3(49, 1, Bn), 192, gemm_smem192>>>(fc2_w, y, h, ps, pss, Cc, C2);
    bn_finalize_kernel<<<1, 256>>>(ps, pss, fc2_g, fc2_be, scale, shift, Cc);
    bn_res_out_kernel<<<(Bn * Cc * Npix) / 1024, 256>>>(h, scale, shift, x, (float*)d_out);
}

// round 13
// speedup vs baseline: 1.4436x; 1.0405x over previous
#include <cuda_runtime.h>
#include <math.h>

#define Bn 8
#define Cc 96
#define C2 192
#define Npix 3136
#define KK 9
#define BNtot 25088       // Bn*Npix
#define NSPLIT 3
#define PSG 392           // 8 batches * 49 n-blocks

// ---------------- scratch ----------------
__device__ float g_h  [Bn*Cc*Npix];
__device__ float g_ht [Bn*Npix*Cc];
__device__ float g_xnt[Bn*Npix*Cc];     // L2-normalized features fp32, (B,N,C)
__device__ float g_xh [Bn*Npix*Cc];     // tf32-hi of normalized features
__device__ float g_xl [Bn*Npix*Cc];     // fp32 residual
__device__ float g_sq [Bn*Npix];
__device__ int   g_idx[Bn*Npix*KK];
__device__ float g_val2[Bn*NSPLIT*Npix*KK];
__device__ int   g_idx2[Bn*NSPLIT*Npix*KK];
__device__ float g_y  [Bn*C2*Npix];
__device__ float g_t1 [Bn*C2*Npix];
__device__ float g_ps [C2*PSG];
__device__ float g_pss[C2*PSG];
__device__ float g_scale[C2];
__device__ float g_shift[C2];

// ---------------- shared helpers ----------------
__device__ __forceinline__ void mma_tf32(float* c, unsigned a0, unsigned a1, unsigned a2, unsigned a3,
                                         unsigned b0, unsigned b1) {
    asm volatile(
        "mma.sync.aligned.m16n8k8.row.col.f32.tf32.tf32.f32 "
        "{%0,%1,%2,%3}, {%4,%5,%6,%7}, {%8,%9}, {%0,%1,%2,%3};\n"
        : "+f"(c[0]), "+f"(c[1]), "+f"(c[2]), "+f"(c[3])
        : "r"(a0), "r"(a1), "r"(a2), "r"(a3), "r"(b0), "r"(b1));
}

__device__ __forceinline__ unsigned hif(float f) {
    return __float_as_uint(f) & 0xFFFFE000u;
}
__device__ __forceinline__ unsigned lof(float f, unsigned h) {
    return __float_as_uint(f - __uint_as_float(h));
}

__device__ __forceinline__ void topk_ins(float (&tv)[9], int (&ti)[9], float s, int m) {
    if (s > tv[8]) {
        tv[8] = s; ti[8] = m;
        #pragma unroll
        for (int p = 8; p > 0; p--) {
            if (tv[p] > tv[p - 1]) {
                float f = tv[p]; tv[p] = tv[p - 1]; tv[p - 1] = f;
                int i = ti[p]; ti[p] = ti[p - 1]; ti[p - 1] = i;
            }
        }
    }
}

// ---------------- tf32 GEMM + fused BN partial stats (no bias: BN cancels it) ----------------
#define TG_PAD 72

__global__ __launch_bounds__(192, 2) void gemm_bn_kernel(
    const float* __restrict__ W, const float* __restrict__ Act,
    float* __restrict__ Out, float* __restrict__ ps, float* __restrict__ pss,
    int M, int Kd)
{
    extern __shared__ float sg[];
    int KSTR = Kd + 4;               // pad: banks 4*gid+tg, conflict-free
    float* A_s = sg;                 // [96][KSTR]
    float* B_s = sg + 96 * KSTR;     // [32][TG_PAD]

    int tid = threadIdx.x;
    int warp = tid >> 5, lane = tid & 31;
    int gid = lane >> 2, tg = lane & 3;
    int b = blockIdx.z;
    int m0 = blockIdx.y * 96;
    int n0 = blockIdx.x * 64;
    int nb = blockIdx.x;

    // stage A = W[m0..m0+95][0..Kd) whole-K (resident)
    {
        int k4n = Kd >> 2;
        const float4* gw = (const float4*)(W + (size_t)m0 * Kd);
        for (int e = tid; e < 96 * k4n; e += 192) {
            int r = e / k4n, k4 = e - r * k4n;
            *(float4*)(A_s + r * KSTR + k4 * 4) = gw[e];
        }
    }

    float ach[8][4], acx[8][4];
    #pragma unroll
    for (int nt = 0; nt < 8; nt++)
        #pragma unroll
        for (int j = 0; j < 4; j++) { ach[nt][j] = 0.f; acx[nt][j] = 0.f; }

    int nch = Kd >> 5;
    for (int kch = 0; kch < nch; kch++) {
        __syncthreads();
        {
            const float* gb = Act + ((size_t)b * Kd + kch * 32) * Npix + n0;
            for (int e = tid; e < 32 * 16; e += 192) {
                int k = e >> 4, n4 = e & 15;
                *(float4*)(B_s + k * TG_PAD + n4 * 4) =
                    *(const float4*)(gb + (size_t)k * Npix + n4 * 4);
            }
        }
        __syncthreads();
        #pragma unroll
        for (int kc = 0; kc < 4; kc++) {
            int ra = (warp * 16 + gid) * KSTR + kch * 32 + kc * 8 + tg;
            float f0 = A_s[ra],     f1 = A_s[ra + 8 * KSTR];
            float f2 = A_s[ra + 4], f3 = A_s[ra + 8 * KSTR + 4];
            unsigned ah0 = hif(f0), ah1 = hif(f1), ah2 = hif(f2), ah3 = hif(f3);
            unsigned al0 = lof(f0, ah0), al1 = lof(f1, ah1), al2 = lof(f2, ah2), al3 = lof(f3, ah3);
            #pragma unroll
            for (int nt = 0; nt < 8; nt++) {
                int bb = (kc * 8 + tg) * TG_PAD + nt * 8 + gid;
                float g0 = B_s[bb], g1 = B_s[bb + 4 * TG_PAD];
                unsigned bh0 = hif(g0), bh1 = hif(g1);
                unsigned bl0 = lof(g0, bh0), bl1 = lof(g1, bh1);
                mma_tf32(ach[nt], ah0, ah1, ah2, ah3, bh0, bh1);
                mma_tf32(acx[nt], ah0, ah1, ah2, ah3, bl0, bl1);
                mma_tf32(acx[nt], al0, al1, al2, al3, bh0, bh1);
            }
        }
    }

    // epilogue: store + per-row BN partials
    int mrow = m0 + warp * 16 + gid;
    float* Crow  = Out + ((size_t)b * M + mrow) * Npix + n0;
    float* Crow8 = Crow + (size_t)8 * Npix;
    float s0 = 0.f, q0 = 0.f, s1 = 0.f, q1 = 0.f;
    #pragma unroll
    for (int nt = 0; nt < 8; nt++) {
        float c0 = ach[nt][0] + acx[nt][0], c1 = ach[nt][1] + acx[nt][1];
        float c2 = ach[nt][2] + acx[nt][2], c3 = ach[nt][3] + acx[nt][3];
        int col = nt * 8 + 2 * tg;
        *(float2*)(Crow + col)  = make_float2(c0, c1);
        *(float2*)(Crow8 + col) = make_float2(c2, c3);
        s0 += c0 + c1; q0 += c0 * c0 + c1 * c1;
        s1 += c2 + c3; q1 += c2 * c2 + c3 * c3;
    }
    #pragma unroll
    for (int off = 2; off > 0; off >>= 1) {
        s0 += __shfl_down_sync(0xffffffffu, s0, off, 4);
        q0 += __shfl_down_sync(0xffffffffu, q0, off, 4);
        s1 += __shfl_down_sync(0xffffffffu, s1, off, 4);
        q1 += __shfl_down_sync(0xffffffffu, q1, off, 4);
    }
    if (tg == 0) {
        size_t sl0 = (size_t)mrow * PSG + b * 49 + nb;
        size_t sl1 = (size_t)(mrow + 8) * PSG + b * 49 + nb;
        ps[sl0] = s0; pss[sl0] = q0;
        ps[sl1] = s1; pss[sl1] = q1;
    }
}

// ---------------- BN finalize ----------------
__global__ void bn_finalize_kernel(
    const float* __restrict__ ps, const float* __restrict__ pss,
    const float* __restrict__ g, const float* __restrict__ be,
    float* __restrict__ scale, float* __restrict__ shift, int C)
{
    int c = blockIdx.x * blockDim.x + threadIdx.x;
    if (c >= C) return;
    float s = 0.f, ss = 0.f;
    for (int i = 0; i < PSG; i++) { s += ps[(size_t)c * PSG + i]; ss += pss[(size_t)c * PSG + i]; }
    float mean = s * (1.0f / (float)BNtot);
    float var  = ss * (1.0f / (float)BNtot) - mean * mean;
    float inv  = rsqrtf(var + 1e-5f);
    float sc = g[c] * inv;
    scale[c] = sc;
    shift[c] = be[c] - mean * sc;
}

// ---------------- BN apply + transpose + L2 normalize + tf32 hi/lo split ----------------
#define BS_STRIDE 67
__global__ __launch_bounds__(256) void bn_norm_kernel(
    const float* __restrict__ Hraw, const float* __restrict__ scale, const float* __restrict__ shift,
    float* __restrict__ Ht, float* __restrict__ Xn, float* __restrict__ Xh, float* __restrict__ Xl,
    float* __restrict__ Sq)
{
    __shared__ float S[Cc * BS_STRIDE];
    __shared__ float R[256];
    __shared__ float RN[64];
    int tid = threadIdx.x;
    int b = blockIdx.y;
    int n0 = blockIdx.x * 64;

    for (int e = tid; e < Cc * 64; e += 256) {
        int c = e >> 6, n = e & 63;
        float v = Hraw[((size_t)b * Cc + c) * Npix + n0 + n] * scale[c] + shift[c];
        S[c * BS_STRIDE + n] = v;
    }
    __syncthreads();
    {
        int n = tid & 63, part = tid >> 6;
        float p = 0.f;
        for (int c = part * 24; c < part * 24 + 24; c++) {
            float v = S[c * BS_STRIDE + n];
            p += v * v;
        }
        R[tid] = p;
    }
    __syncthreads();
    if (tid < 64) {
        float ssum = R[tid] + R[tid + 64] + R[tid + 128] + R[tid + 192];
        float rn = 1.0f / fmaxf(sqrtf(ssum), 1e-12f);
        Sq[(size_t)b * Npix + n0 + tid] = ssum * rn * rn;
        RN[tid] = rn;
    }
    __syncthreads();
    for (int e = tid; e < Cc * 64; e += 256) {
        int n = e / Cc, c = e - Cc * n;
        float v = S[c * BS_STRIDE + n];
        size_t o = ((size_t)b * Npix + n0 + n) * Cc + c;
        Ht[o] = v;
        float xn = v * RN[n];
        float hi = __uint_as_float(__float_as_uint(xn) & 0xFFFFE000u);
        Xn[o] = xn;
        Xh[o] = hi;
        Xl[o] = xn - hi;
    }
}

// ---------------- fused similarity GEMM (tf32 split mma, cp.async double-buffered B) + top-9 ----------------
#define SAB 100
#define SM_AH 0
#define SM_AL 6400
#define SM_B0 12800
#define SM_B1 19200
#define SM_SQ0 25600
#define SM_SQ1 25664
#define KNN_SMEM_FLOATS 25728
#define KNN_SMEM_BYTES (KNN_SMEM_FLOATS*4)
#define MRG 73

__device__ __forceinline__ void knn_stage_async(
    float* sm, int buf, const float4* XnB, const float* SqB, int m0, int tid)
{
    float* dst = sm + (buf ? SM_B1 : SM_B0);
    const float4* src = XnB + m0 * 24;
    #pragma unroll
    for (int u = 0; u < 6; u++) {
        int f = tid + u * 256;
        int r = f / 24, k4 = f - r * 24;
        unsigned d = (unsigned)__cvta_generic_to_shared(dst + r * SAB + k4 * 4);
        asm volatile("cp.async.cg.shared.global [%0], [%1], 16;\n" :: "r"(d), "l"(src + f));
    }
    if (tid < 16) {
        float* sqd = sm + (buf ? SM_SQ1 : SM_SQ0) + tid * 4;
        unsigned d = (unsigned)__cvta_generic_to_shared(sqd);
        asm volatile("cp.async.cg.shared.global [%0], [%1], 16;\n" :: "r"(d), "l"(SqB + m0 + tid * 4));
    }
    asm volatile("cp.async.commit_group;\n");
}

__global__ __launch_bounds__(256, 2) void knn_kernel(
    const float* __restrict__ Xh, const float* __restrict__ Xl,
    const float* __restrict__ Xn, const float* __restrict__ Sq,
    float* __restrict__ Val2, int* __restrict__ Idx2)
{
    extern __shared__ float sm[];
    const unsigned* uAH = (const unsigned*)(sm + SM_AH);
    const unsigned* uAL = (const unsigned*)(sm + SM_AL);

    int tid = threadIdx.x;
    int warp = tid >> 5, lane = tid & 31;
    int gid = lane >> 2, tg = lane & 3;
    int rbase = (warp & 3) * 16;  // row strip
    int ch = warp >> 2;           // candidate-column half (0/1)
    int b = blockIdx.z;
    int split = blockIdx.y;       // 0..2
    int row0 = blockIdx.x * 64;
    int t0 = (split == 0) ? 0 : (17 + 16 * (split - 1));
    int tc = (split == 0) ? 17 : 16;

    const float4* XhB = (const float4*)(Xh + (size_t)b * Npix * Cc);
    const float4* XlB = (const float4*)(Xl + (size_t)b * Npix * Cc);
    const float4* XnB = (const float4*)(Xn + (size_t)b * Npix * Cc);
    const float*  SqB = Sq + (size_t)b * Npix;

    // stage A tiles (resident): straight float4 copies of precomputed hi/lo
    {
        int abase = row0 * 24;
        for (int f = tid; f < 64 * 24; f += 256) {
            int r = f / 24, k4 = f - r * 24;
            *(float4*)(sm + SM_AH + r * SAB + k4 * 4) = XhB[abase + f];
            *(float4*)(sm + SM_AL + r * SAB + k4 * 4) = XlB[abase + f];
        }
    }

    // prologue: async-stage first B tile
    knn_stage_async(sm, 0, XnB, SqB, t0 * 64, tid);

    float tvA[KK], tvB[KK]; int tiA[KK], tiB[KK];
    #pragma unroll
    for (int q = 0; q < KK; q++) { tvA[q] = -1e30f; tvB[q] = -1e30f; tiA[q] = 0; tiB[q] = 0; }

    for (int i = 0; i < tc; i++) {
        int cur = i & 1;
        int m0 = (t0 + i) * 64;
        asm volatile("cp.async.wait_group 0;\n" ::: "memory");
        __syncthreads();
        if (i + 1 < tc)
            knn_stage_async(sm, 1 - cur, XnB, SqB, (t0 + i + 1) * 64, tid);

        const float* Bt  = sm + (cur ? SM_B1 : SM_B0);
        const float* SqS = sm + (cur ? SM_SQ1 : SM_SQ0);

        float ach[4][4], acx[4][4];
        #pragma unroll
        for (int nt = 0; nt < 4; nt++)
            #pragma unroll
            for (int j = 0; j < 4; j++) { ach[nt][j] = 0.f; acx[nt][j] = 0.f; }

        #pragma unroll
        for (int kc = 0; kc < 12; kc++) {
            int k0 = kc * 8;
            int ra = (rbase + gid) * SAB + k0 + tg;
            unsigned ah0 = uAH[ra],     ah1 = uAH[ra + 8 * SAB];
            unsigned ah2 = uAH[ra + 4], ah3 = uAH[ra + 8 * SAB + 4];
            unsigned al0 = uAL[ra],     al1 = uAL[ra + 8 * SAB];
            unsigned al2 = uAL[ra + 4], al3 = uAL[ra + 8 * SAB + 4];
            #pragma unroll
            for (int nt = 0; nt < 4; nt++) {
                int nb = (ch * 32 + nt * 8 + gid) * SAB + k0 + tg;
                float g0 = Bt[nb], g1 = Bt[nb + 4];
                unsigned bh0 = hif(g0), bh1 = hif(g1);
                unsigned bl0 = lof(g0, bh0), bl1 = lof(g1, bh1);
                // hl, hh, lh: per-accumulator order (acx: hl->lh) as rounds 10-12.
                mma_tf32(acx[nt], ah0, ah1, ah2, ah3, bl0, bl1);
                mma_tf32(ach[nt], ah0, ah1, ah2, ah3, bh0, bh1);
                mma_tf32(acx[nt], al0, al1, al2, al3, bh0, bh1);
            }
        }

        // scores + in-register top-9 (rows rbase+gid and rbase+gid+8)
        #pragma unroll
        for (int nt = 0; nt < 4; nt++) {
            int c = ch * 32 + nt * 8 + 2 * tg;
            float sq0 = SqS[c];
            float sq1 = SqS[c + 1];
            int m = m0 + c;
            float s0 = fmaf(2.f, ach[nt][0] + acx[nt][0], -sq0);
            float s1 = fmaf(2.f, ach[nt][1] + acx[nt][1], -sq1);
            float s2 = fmaf(2.f, ach[nt][2] + acx[nt][2], -sq0);
            float s3 = fmaf(2.f, ach[nt][3] + acx[nt][3], -sq1);
            topk_ins(tvA, tiA, s0, m);
            topk_ins(tvA, tiA, s1, m + 1);
            topk_ins(tvB, tiB, s2, m);
            topk_ins(tvB, tiB, s3, m + 1);
        }
    }
    __syncthreads();

    // merge 8 per-row lists (4 lanes x 2 col-halves); alias over A-tile regions
    float* mv = sm;                      // [64][MRG] (72 used)
    int*   mi = (int*)(sm + 64 * MRG);   // [64][MRG]
    int list = ch * 4 + tg;
    int la = rbase + gid;
    #pragma unroll
    for (int q = 0; q < KK; q++) {
        mv[la * MRG + list * KK + q] = tvA[q];
        mi[la * MRG + list * KK + q] = tiA[q];
        mv[(la + 8) * MRG + list * KK + q] = tvB[q];
        mi[(la + 8) * MRG + list * KK + q] = tiB[q];
    }
    __syncthreads();
    if (tid < 64) {
        float* crow = &mv[tid * MRG];
        int*   irow = &mi[tid * MRG];
        size_t base = ((size_t)(b * NSPLIT + split) * Npix + row0 + tid) * KK;
        #pragma unroll
        for (int q = 0; q < KK; q++) {
            float best = -3.0e38f; int bi = 0x7fffffff, bj = 0;
            for (int j = 0; j < 72; j++) {
                float v = crow[j]; int id = irow[j];
                if (v > best || (v == best && id < bi)) { best = v; bi = id; bj = j; }
            }
            Val2[base + q] = best;
            Idx2[base + q] = bi;
            crow[bj] = -3.0e38f;
            irow[bj] = 0x7fffffff;
        }
    }
}

// ---------------- cross-split merge (3-way) ----------------
__global__ __launch_bounds__(256) void knn_merge_kernel(
    const float* __restrict__ Val2, const int* __restrict__ Idx2, int* __restrict__ Idx)
{
    int i = blockIdx.x * 256 + threadIdx.x;
    if (i >= Bn * Npix) return;
    int b = i / Npix, n = i - b * Npix;
    size_t base[NSPLIT];
    int p[NSPLIT];
    #pragma unroll
    for (int s = 0; s < NSPLIT; s++) {
        base[s] = ((size_t)(b * NSPLIT + s) * Npix + n) * KK;
        p[s] = 0;
    }
    int* o = Idx + ((size_t)b * Npix + n) * KK;
    #pragma unroll
    for (int k = 0; k < KK; k++) {
        float bv = -3.0e38f; int bi = 0x7fffffff, bs = 0;
        #pragma unroll
        for (int s = 0; s < NSPLIT; s++) {
            if (p[s] < KK) {
                float v = Val2[base[s] + p[s]];
                int id = Idx2[base[s] + p[s]];
                if (v > bv || (v == bv && id < bi)) { bv = v; bi = id; bs = s; }
            }
        }
        o[k] = bi;
        p[bs]++;
    }
}

// ---------------- gather + max-relative + interleave ----------------
__global__ __launch_bounds__(256) void build_y_kernel(
    const float* __restrict__ Ht, const int* __restrict__ Idx, float* __restrict__ Y)
{
    __shared__ int sidx[32 * KK];
    __shared__ float T[C2 * 33];
    int tid = threadIdx.x;
    int b = blockIdx.y;
    int n0 = blockIdx.x * 32;
    const float* hb = Ht + (size_t)b * Npix * Cc;

    for (int e = tid; e < 32 * KK; e += 256)
        sidx[e] = Idx[((size_t)b * Npix + n0) * KK + e];
    __syncthreads();

    int nl = tid >> 3, part = tid & 7;
    int c0 = part * 12;
    const float4* hr = (const float4*)(hb + (size_t)(n0 + nl) * Cc + c0);
    float4 v0 = hr[0], v1 = hr[1], v2 = hr[2];
    float v[12] = {v0.x, v0.y, v0.z, v0.w, v1.x, v1.y, v1.z, v1.w, v2.x, v2.y, v2.z, v2.w};
    float mx[12];
    #pragma unroll
    for (int j = 0; j < 12; j++) mx[j] = -1e30f;
    #pragma unroll
    for (int k = 0; k < KK; k++) {
        const float4* hn = (const float4*)(hb + (size_t)sidx[nl * KK + k] * Cc + c0);
        float4 a = hn[0], c = hn[1], d = hn[2];
        float w[12] = {a.x, a.y, a.z, a.w, c.x, c.y, c.z, c.w, d.x, d.y, d.z, d.w};
        #pragma unroll
        for (int j = 0; j < 12; j++) mx[j] = fmaxf(mx[j], w[j]);
    }
    #pragma unroll
    for (int j = 0; j < 12; j++) {
        int c = c0 + j;
        T[(2 * c) * 33 + nl]     = v[j];
        T[(2 * c + 1) * 33 + nl] = mx[j] - v[j];
    }
    __syncthreads();
    float* yb = Y + (size_t)b * C2 * Npix;
    for (int e = tid; e < C2 * 32; e += 256) {
        int r = e >> 5, n = e & 31;
        yb[(size_t)r * Npix + n0 + n] = T[r * 33 + n];
    }
}

// ---------------- BN apply + exact GELU (float4) ----------------
__global__ __launch_bounds__(256) void bn_act_kernel(
    float* __restrict__ X, const float* __restrict__ scale, const float* __restrict__ shift, int C)
{
    size_t i = (size_t)blockIdx.x * 256 + threadIdx.x;
    int c = (int)((i * 4 / Npix) % C);
    float sc = scale[c], sh = shift[c];
    float4 v = ((float4*)X)[i];
    float a[4] = {v.x, v.y, v.z, v.w};
    #pragma unroll
    for (int j = 0; j < 4; j++) {
        float t = a[j] * sc + sh;
        a[j] = 0.5f * t * (1.0f + erff(t * 0.70710678118654752f));
    }
    ((float4*)X)[i] = make_float4(a[0], a[1], a[2], a[3]);
}

// ---------------- final BN + residual (float4) ----------------
__global__ __launch_bounds__(256) void bn_res_out_kernel(
    const float* __restrict__ raw, const float* __restrict__ scale, const float* __restrict__ shift,
    const float* __restrict__ x, float* __restrict__ out)
{
    size_t i = (size_t)blockIdx.x * 256 + threadIdx.x;
    int c = (int)((i * 4 / Npix) % Cc);
    float sc = scale[c], sh = shift[c];
    float4 r = ((const float4*)raw)[i];
    float4 xv = ((const float4*)x)[i];
    float4 o;
    o.x = r.x * sc + sh + xv.x;
    o.y = r.y * sc + sh + xv.y;
    o.z = r.z * sc + sh + xv.z;
    o.w = r.w * sc + sh + xv.w;
    ((float4*)out)[i] = o;
}

// ---------------- launch ----------------
extern "C" void kernel_launch(void* const* d_in, const int* in_sizes, int n_in,
                              void* d_out, int out_size)
{
    const float* x      = (const float*)d_in[0];
    const float* fc1_w  = (const float*)d_in[1];
    const float* fc1_g  = (const float*)d_in[3];
    const float* fc1_be = (const float*)d_in[4];
    const float* g1_w   = (const float*)d_in[5];
    const float* g1_g   = (const float*)d_in[7];
    const float* g1_be  = (const float*)d_in[8];
    const float* g2_w   = (const float*)d_in[9];
    const float* g2_g   = (const float*)d_in[11];
    const float* g2_be  = (const float*)d_in[12];
    const float* fc2_w  = (const float*)d_in[13];
    const float* fc2_g  = (const float*)d_in[15];
    const float* fc2_be = (const float*)d_in[16];

    float *h, *ht, *xnt, *xh, *xl, *sq, *y, *t1, *ps, *pss, *scale, *shift, *val2;
    int *idx, *idx2;
    cudaGetSymbolAddress((void**)&h,     g_h);
    cudaGetSymbolAddress((void**)&ht,    g_ht);
    cudaGetSymbolAddress((void**)&xnt,   g_xnt);
    cudaGetSymbolAddress((void**)&xh,    g_xh);
    cudaGetSymbolAddress((void**)&xl,    g_xl);
    cudaGetSymbolAddress((void**)&sq,    g_sq);
    cudaGetSymbolAddress((void**)&idx,   g_idx);
    cudaGetSymbolAddress((void**)&val2,  g_val2);
    cudaGetSymbolAddress((void**)&idx2,  g_idx2);
    cudaGetSymbolAddress((void**)&y,     g_y);
    cudaGetSymbolAddress((void**)&t1,    g_t1);
    cudaGetSymbolAddress((void**)&ps,    g_ps);
    cudaGetSymbolAddress((void**)&pss,   g_pss);
    cudaGetSymbolAddress((void**)&scale, g_scale);
    cudaGetSymbolAddress((void**)&shift, g_shift);

    int gemm_smem96  = (96 * (Cc + 4) + 32 * TG_PAD) * 4;   // Kd=96
    int gemm_smem192 = (96 * (C2 + 4) + 32 * TG_PAD) * 4;   // Kd=192
    cudaFuncSetAttribute(knn_kernel, cudaFuncAttributeMaxDynamicSharedMemorySize, KNN_SMEM_BYTES);
    cudaFuncSetAttribute(gemm_bn_kernel, cudaFuncAttributeMaxDynamicSharedMemorySize, gemm_smem192);

    // fc1 (bias dropped: cancels in BN)
    gemm_bn_kernel<<<dim3(49, 1, Bn), 192, gemm_smem96>>>(fc1_w, x, h, ps, pss, Cc, Cc);
    bn_finalize_kernel<<<1, 256>>>(ps, pss, fc1_g, fc1_be, scale, shift, Cc);
    bn_norm_kernel<<<dim3(Npix / 64, Bn), 256>>>(h, scale, shift, ht, xnt, xh, xl, sq);

    // knn (tf32 split mma, cp.async double-buffered B, 3 candidate splits) + merge
    knn_kernel<<<dim3(Npix / 64, NSPLIT, Bn), 256, KNN_SMEM_BYTES>>>(xh, xl, xnt, sq, val2, idx2);
    knn_merge_kernel<<<(Bn * Npix + 255) / 256, 256>>>(val2, idx2, idx);

    // gather + interleave
    build_y_kernel<<<dim3(Npix / 32, Bn), 256>>>(ht, idx, y);

    // g1
    gemm_bn_kernel<<<dim3(49, 2, Bn), 192, gemm_smem192>>>(g1_w, y, t1, ps, pss, C2, C2);
    bn_finalize_kernel<<<1, 256>>>(ps, pss, g1_g, g1_be, scale, shift, C2);
    bn_act_kernel<<<(Bn * C2 * Npix) / 1024, 256>>>(t1, scale, shift, C2);

    // g2
    gemm_bn_kernel<<<dim3(49, 2, Bn), 192, gemm_smem192>>>(g2_w, t1, y, ps, pss, C2, C2);
    bn_finalize_kernel<<<1, 256>>>(ps, pss, g2_g, g2_be, scale, shift, C2);
    bn_act_kernel<<<(Bn * C2 * Npix) / 1024, 256>>>(y, scale, shift, C2);

    // fc2
    gemm_bn_kernel<<<dim3(49, 1, Bn), 192, gemm_smem192>>>(fc2_w, y, h, ps, pss, Cc, C2);
    bn_finalize_kernel<<<1, 256>>>(ps, pss, fc2_g, fc2_be, scale, shift, Cc);
    bn_res_out_kernel<<<(Bn * Cc * Npix) / 1024, 256>>>(h, scale, shift, x, (float*)d_out);
}